// round 12
// baseline (speedup 1.0000x reference)
#include <cuda_runtime.h>
#include <math.h>

#define NN 50000
#define EE 400000
#define EL 450000   // E + N self loops
#define ED 32

// ---------------- scratch (static device globals; no allocation) -------------
__device__ float g_h[NN * 256];      // projected features
__device__ float g_act[NN * 256];    // activated layer input (layers 2,3)
__device__ float g_loop[NN * ED];    // loop_attr (segment mean of edge_attr)
__device__ float g_ai[3 * NN * 4];   // per-layer node attention scalars (i)
__device__ float g_aj[3 * NN * 4];   // per-layer node attention scalars (j)
__device__ float g_wtI[3 * 1024];    // per-layer projected att vectors (W @ att_i)
__device__ float g_wtJ[3 * 1024];
__device__ float g_alpha[EL * 4];    // exp weights, sorted by dst
__device__ float g_eatt[3 * EL * 4]; // per-layer edge-MLP attention term (by edge id)
__device__ int   g_rowptr[NN + 1];
__device__ int   g_cnt[NN];
__device__ int   g_col_src[EL];      // src node per sorted edge
__device__ int   g_col_eid[EL];      // original edge id per sorted edge
__device__ int   g_perm[EL];         // original edge -> sorted position

// ---------------- CSR build ----------------------------------------------------
__global__ void initcnt_kernel() {
    int i = blockIdx.x * blockDim.x + threadIdx.x;
    if (i < NN) g_cnt[i] = 1;        // self loop
}

__global__ void hist_kernel(const int* __restrict__ dst) {
    int e = blockIdx.x * blockDim.x + threadIdx.x;
    if (e < EE) atomicAdd(&g_cnt[dst[e]], 1);
}

__global__ void scan_kernel() {
    __shared__ int sb[1024];
    int t = threadIdx.x;
    const int CH = (NN + 1023) / 1024;
    int lo = t * CH;
    int hi = min(lo + CH, NN);
    int s = 0;
    for (int i = lo; i < hi; i++) s += g_cnt[i];
    sb[t] = s;
    __syncthreads();
    for (int off = 1; off < 1024; off <<= 1) {
        int v = (t >= off) ? sb[t - off] : 0;
        __syncthreads();
        sb[t] += v;
        __syncthreads();
    }
    int run = (t > 0) ? sb[t - 1] : 0;
    for (int i = lo; i < hi; i++) {
        g_rowptr[i] = run;
        run += g_cnt[i];
        g_cnt[i] = 0;               // reset for scatter fill
    }
    if (t == 0) g_rowptr[NN] = EL;
}

__global__ void scatter_kernel(const int* __restrict__ src, const int* __restrict__ dst) {
    int e = blockIdx.x * blockDim.x + threadIdx.x;
    if (e >= EL) return;
    int s, d;
    if (e < EE) { s = src[e]; d = dst[e]; }
    else        { s = d = e - EE; }
    int pos = g_rowptr[d] + atomicAdd(&g_cnt[d], 1);
    g_col_src[pos] = s;
    g_col_eid[pos] = e;
    g_perm[e] = pos;
}

// loop_attr: per-node mean of incoming real-edge attrs (warp/node, lane = dim)
__global__ void loop_attr_kernel(const float* __restrict__ ea) {
    int w = (blockIdx.x * blockDim.x + threadIdx.x) >> 5;
    int lane = threadIdx.x & 31;
    if (w >= NN) return;
    int p0 = g_rowptr[w], p1 = g_rowptr[w + 1];
    float s = 0.f;
    int c = 0;
    for (int p = p0; p < p1; p++) {
        int eid = g_col_eid[p];
        if (eid < EE) { s += ea[(size_t)eid * ED + lane]; c++; }
    }
    g_loop[w * ED + lane] = (c > 0) ? s / (float)c : 0.f;
}

// ---------------- wtilde: w̃[h,k] = sum_c W[k, h*out_c+c] * att_{i/j}[h,c] ------
__global__ void wt_kernel(const float* __restrict__ W, const float* __restrict__ att,
                          int K, int Nout, int out_c, int heads,
                          float* __restrict__ wtI, float* __restrict__ wtJ) {
    int t = blockIdx.x * blockDim.x + threadIdx.x;
    if (t >= heads * K) return;
    int h = t / K, k = t - h * K;
    int stride = 2 * out_c + ED;
    const float* Wr  = W + (size_t)k * Nout + h * out_c;
    const float* ati = att + h * stride;
    const float* atj = ati + out_c;
    float si = 0.f, sj = 0.f;
    for (int c = 0; c < out_c; c++) {
        float w = Wr[c];
        si += w * ati[c];
        sj += w * atj[c];
    }
    wtI[t] = si;
    wtJ[t] = sj;
}

// ---------------- ai GEMV: a[n,h] = dot(A[n,:], w̃[h,:]); A==null -> g_act -----
__global__ void ai4_kernel(const float* A, int K,
                           const float* __restrict__ wtI, const float* __restrict__ wtJ,
                           float* __restrict__ ai, float* __restrict__ aj) {
    __shared__ float sI[1024], sJ[1024];
    const float* base = A ? A : g_act;
    int tid = threadIdx.x;
    for (int i = tid; i < 4 * K; i += 256) { sI[i] = wtI[i]; sJ[i] = wtJ[i]; }
    __syncthreads();
    int gw = (blockIdx.x * blockDim.x + tid) >> 5;
    int lane = tid & 31;
    if (gw >= NN) return;
    const float* Ap = base + (size_t)gw * K;
    float i0 = 0.f, i1 = 0.f, i2 = 0.f, i3 = 0.f;
    float j0 = 0.f, j1 = 0.f, j2 = 0.f, j3 = 0.f;
    for (int k = lane; k < K; k += 32) {
        float v = Ap[k];
        i0 += v * sI[k];         i1 += v * sI[K + k];
        i2 += v * sI[2 * K + k]; i3 += v * sI[3 * K + k];
        j0 += v * sJ[k];         j1 += v * sJ[K + k];
        j2 += v * sJ[2 * K + k]; j3 += v * sJ[3 * K + k];
    }
#pragma unroll
    for (int o = 16; o > 0; o >>= 1) {
        i0 += __shfl_xor_sync(0xffffffffu, i0, o);
        i1 += __shfl_xor_sync(0xffffffffu, i1, o);
        i2 += __shfl_xor_sync(0xffffffffu, i2, o);
        i3 += __shfl_xor_sync(0xffffffffu, i3, o);
        j0 += __shfl_xor_sync(0xffffffffu, j0, o);
        j1 += __shfl_xor_sync(0xffffffffu, j1, o);
        j2 += __shfl_xor_sync(0xffffffffu, j2, o);
        j3 += __shfl_xor_sync(0xffffffffu, j3, o);
    }
    if (lane == 0) {
        *(float4*)(ai + (size_t)gw * 4) = make_float4(i0, i1, i2, i3);
        *(float4*)(aj + (size_t)gw * 4) = make_float4(j0, j1, j2, j3);
    }
}

__global__ void ai1_kernel(const float* A, int K,
                           const float* __restrict__ wtI, const float* __restrict__ wtJ,
                           float* __restrict__ ai, float* __restrict__ aj) {
    __shared__ float sI[256], sJ[256];
    const float* base = A ? A : g_act;
    int tid = threadIdx.x;
    for (int i = tid; i < K; i += 256) { sI[i] = wtI[i]; sJ[i] = wtJ[i]; }
    __syncthreads();
    int gw = (blockIdx.x * blockDim.x + tid) >> 5;
    int lane = tid & 31;
    if (gw >= NN) return;
    const float* Ap = base + (size_t)gw * K;
    float i0 = 0.f, j0 = 0.f;
    for (int k = lane; k < K; k += 32) {
        float v = Ap[k];
        i0 += v * sI[k];
        j0 += v * sJ[k];
    }
#pragma unroll
    for (int o = 16; o > 0; o >>= 1) {
        i0 += __shfl_xor_sync(0xffffffffu, i0, o);
        j0 += __shfl_xor_sync(0xffffffffu, j0, o);
    }
    if (lane == 0) { ai[gw] = i0; aj[gw] = j0; }
}

// ---------------- GEMM A: 128x128x8 tile, 8x8 micro-tile (R10-proven) ---------
__global__ void gemm128_kernel(const float* __restrict__ x_ext, int use_ext,
                               const float* __restrict__ W, int K, int Nout) {
    __shared__ float As[2][8][132];
    __shared__ float Bs[2][8][128];
    const float* A = use_ext ? x_ext : g_act;
    int t = threadIdx.x;
    int tx = t & 15;
    int ty = t >> 4;
    int row0 = blockIdx.x * 128, col0 = blockIdx.y * 128;

    int ar = t >> 1, ak = (t & 1) * 4;
    int arow = min(row0 + ar, NN - 1);
    const float* Ap = A + (size_t)arow * K + ak;
    int br = t >> 5, bc = (t & 31) * 4;
    const float* Wp = W + (size_t)br * Nout + col0 + bc;

    int ktiles = K >> 3;
    float4 pa = *(const float4*)(Ap);
    float4 pb = *(const float4*)(Wp);

    float acc[8][8];
#pragma unroll
    for (int i = 0; i < 8; i++)
#pragma unroll
        for (int j = 0; j < 8; j++) acc[i][j] = 0.f;

    for (int kt = 0; kt < ktiles; kt++) {
        int cbuf = kt & 1;
        As[cbuf][ak + 0][ar] = pa.x;
        As[cbuf][ak + 1][ar] = pa.y;
        As[cbuf][ak + 2][ar] = pa.z;
        As[cbuf][ak + 3][ar] = pa.w;
        *(float4*)&Bs[cbuf][br][bc] = pb;
        __syncthreads();

        if (kt + 1 < ktiles) {
            int k0 = (kt + 1) << 3;
            pa = *(const float4*)(Ap + k0);
            pb = *(const float4*)(Wp + (size_t)k0 * Nout);
        }

#pragma unroll
        for (int kk = 0; kk < 8; kk++) {
            float4 a0 = *(const float4*)&As[cbuf][kk][ty * 8];
            float4 a1 = *(const float4*)&As[cbuf][kk][ty * 8 + 4];
            float4 b0 = *(const float4*)&Bs[cbuf][kk][tx * 8];
            float4 b1 = *(const float4*)&Bs[cbuf][kk][tx * 8 + 4];
            acc[0][0] += a0.x * b0.x; acc[0][1] += a0.x * b0.y; acc[0][2] += a0.x * b0.z; acc[0][3] += a0.x * b0.w;
            acc[0][4] += a0.x * b1.x; acc[0][5] += a0.x * b1.y; acc[0][6] += a0.x * b1.z; acc[0][7] += a0.x * b1.w;
            acc[1][0] += a0.y * b0.x; acc[1][1] += a0.y * b0.y; acc[1][2] += a0.y * b0.z; acc[1][3] += a0.y * b0.w;
            acc[1][4] += a0.y * b1.x; acc[1][5] += a0.y * b1.y; acc[1][6] += a0.y * b1.z; acc[1][7] += a0.y * b1.w;
            acc[2][0] += a0.z * b0.x; acc[2][1] += a0.z * b0.y; acc[2][2] += a0.z * b0.z; acc[2][3] += a0.z * b0.w;
            acc[2][4] += a0.z * b1.x; acc[2][5] += a0.z * b1.y; acc[2][6] += a0.z * b1.z; acc[2][7] += a0.z * b1.w;
            acc[3][0] += a0.w * b0.x; acc[3][1] += a0.w * b0.y; acc[3][2] += a0.w * b0.z; acc[3][3] += a0.w * b0.w;
            acc[3][4] += a0.w * b1.x; acc[3][5] += a0.w * b1.y; acc[3][6] += a0.w * b1.z; acc[3][7] += a0.w * b1.w;
            acc[4][0] += a1.x * b0.x; acc[4][1] += a1.x * b0.y; acc[4][2] += a1.x * b0.z; acc[4][3] += a1.x * b0.w;
            acc[4][4] += a1.x * b1.x; acc[4][5] += a1.x * b1.y; acc[4][6] += a1.x * b1.z; acc[4][7] += a1.x * b1.w;
            acc[5][0] += a1.y * b0.x; acc[5][1] += a1.y * b0.y; acc[5][2] += a1.y * b0.z; acc[5][3] += a1.y * b0.w;
            acc[5][4] += a1.y * b1.x; acc[5][5] += a1.y * b1.y; acc[5][6] += a1.y * b1.z; acc[5][7] += a1.y * b1.w;
            acc[6][0] += a1.z * b0.x; acc[6][1] += a1.z * b0.y; acc[6][2] += a1.z * b0.z; acc[6][3] += a1.z * b0.w;
            acc[6][4] += a1.z * b1.x; acc[6][5] += a1.z * b1.y; acc[6][6] += a1.z * b1.z; acc[6][7] += a1.z * b1.w;
            acc[7][0] += a1.w * b0.x; acc[7][1] += a1.w * b0.y; acc[7][2] += a1.w * b0.z; acc[7][3] += a1.w * b0.w;
            acc[7][4] += a1.w * b1.x; acc[7][5] += a1.w * b1.y; acc[7][6] += a1.w * b1.z; acc[7][7] += a1.w * b1.w;
        }
        __syncthreads();
    }

    int gcol = col0 + tx * 8;
#pragma unroll
    for (int i = 0; i < 8; i++) {
        int gr = row0 + ty * 8 + i;
        if (gr < NN) {
            *(float4*)&g_h[(size_t)gr * Nout + gcol]     = make_float4(acc[i][0], acc[i][1], acc[i][2], acc[i][3]);
            *(float4*)&g_h[(size_t)gr * Nout + gcol + 4] = make_float4(acc[i][4], acc[i][5], acc[i][6], acc[i][7]);
        }
    }
}

// ---------------- GEMM B: 128x64x16 tile, 8x4 micro-tile (R10-proven) ---------
__global__ void gemm64_kernel(const float* __restrict__ x_ext, int use_ext,
                              const float* __restrict__ W, int K, int Nout) {
    __shared__ float As[2][16][132];
    __shared__ float Bs[2][16][64];
    const float* A = use_ext ? x_ext : g_act;
    int t = threadIdx.x;
    int tx = t & 15;
    int ty = t >> 4;
    int row0 = blockIdx.x * 128, col0 = blockIdx.y * 64;

    int ar0 = t >> 2, ak = (t & 3) * 4;
    int arowA = min(row0 + ar0,      NN - 1);
    int arowB = min(row0 + ar0 + 64, NN - 1);
    const float* ApA = A + (size_t)arowA * K + ak;
    const float* ApB = A + (size_t)arowB * K + ak;
    int br = t >> 4, bc = (t & 15) * 4;
    const float* Wp = W + (size_t)br * Nout + col0 + bc;

    int ktiles = K >> 4;
    float4 pa0 = *(const float4*)(ApA);
    float4 pa1 = *(const float4*)(ApB);
    float4 pb  = *(const float4*)(Wp);

    float acc[8][4];
#pragma unroll
    for (int i = 0; i < 8; i++)
#pragma unroll
        for (int j = 0; j < 4; j++) acc[i][j] = 0.f;

    for (int kt = 0; kt < ktiles; kt++) {
        int cbuf = kt & 1;
        As[cbuf][ak + 0][ar0] = pa0.x;  As[cbuf][ak + 1][ar0] = pa0.y;
        As[cbuf][ak + 2][ar0] = pa0.z;  As[cbuf][ak + 3][ar0] = pa0.w;
        As[cbuf][ak + 0][ar0 + 64] = pa1.x;  As[cbuf][ak + 1][ar0 + 64] = pa1.y;
        As[cbuf][ak + 2][ar0 + 64] = pa1.z;  As[cbuf][ak + 3][ar0 + 64] = pa1.w;
        *(float4*)&Bs[cbuf][br][bc] = pb;
        __syncthreads();

        if (kt + 1 < ktiles) {
            int k0 = (kt + 1) << 4;
            pa0 = *(const float4*)(ApA + k0);
            pa1 = *(const float4*)(ApB + k0);
            pb  = *(const float4*)(Wp + (size_t)k0 * Nout);
        }

#pragma unroll
        for (int kk = 0; kk < 16; kk++) {
            float4 a0 = *(const float4*)&As[cbuf][kk][ty * 8];
            float4 a1 = *(const float4*)&As[cbuf][kk][ty * 8 + 4];
            float4 b  = *(const float4*)&Bs[cbuf][kk][tx * 4];
            acc[0][0] += a0.x * b.x; acc[0][1] += a0.x * b.y; acc[0][2] += a0.x * b.z; acc[0][3] += a0.x * b.w;
            acc[1][0] += a0.y * b.x; acc[1][1] += a0.y * b.y; acc[1][2] += a0.y * b.z; acc[1][3] += a0.y * b.w;
            acc[2][0] += a0.z * b.x; acc[2][1] += a0.z * b.y; acc[2][2] += a0.z * b.z; acc[2][3] += a0.z * b.w;
            acc[3][0] += a0.w * b.x; acc[3][1] += a0.w * b.y; acc[3][2] += a0.w * b.z; acc[3][3] += a0.w * b.w;
            acc[4][0] += a1.x * b.x; acc[4][1] += a1.x * b.y; acc[4][2] += a1.x * b.z; acc[4][3] += a1.x * b.w;
            acc[5][0] += a1.y * b.x; acc[5][1] += a1.y * b.y; acc[5][2] += a1.y * b.z; acc[5][3] += a1.y * b.w;
            acc[6][0] += a1.z * b.x; acc[6][1] += a1.z * b.y; acc[6][2] += a1.z * b.z; acc[6][3] += a1.z * b.w;
            acc[7][0] += a1.w * b.x; acc[7][1] += a1.w * b.y; acc[7][2] += a1.w * b.z; acc[7][3] += a1.w * b.w;
        }
        __syncthreads();
    }

    int gcol = col0 + tx * 4;
#pragma unroll
    for (int i = 0; i < 8; i++) {
        int gr = row0 + ty * 8 + i;
        if (gr < NN)
            *(float4*)&g_h[(size_t)gr * Nout + gcol] =
                make_float4(acc[i][0], acc[i][1], acc[i][2], acc[i][3]);
    }
}

// ---------------- edge_pre: gating MLP -> g_eatt (h-independent) --------------
__global__ void edge_pre_kernel(const float* __restrict__ eattr,
                                const float* __restrict__ ew1, const float* __restrict__ eb1,
                                const float* __restrict__ ew2, const float* __restrict__ eb2,
                                const float* __restrict__ att,
                                int heads, int out_c, int lay) {
    __shared__ float sEA[32][260];
    __shared__ float sW1[32 * 16], sB1[16], sW2[16 * 32], sB2[32], sAE[4 * 32];
    int tid = threadIdx.x;
    int base = blockIdx.x * 256;
    int stride = 2 * out_c + ED;

    for (int i = tid; i < 512; i += 128) { sW1[i] = ew1[i]; sW2[i] = ew2[i]; }
    if (tid < 16) sB1[tid] = eb1[tid];
    if (tid < 32) sB2[tid] = eb2[tid];
    for (int i = tid; i < heads * 32; i += 128) {
        int h = i >> 5, k = i & 31;
        sAE[i] = att[h * stride + 2 * out_c + k];
    }
    for (int i = tid; i < 256 * 8; i += 128) {
        int row = i >> 3, q = i & 7;
        int ge = base + row;
        if (ge < EL) {
            const float4* p = (ge < EE) ? (const float4*)(eattr + (size_t)ge * 32)
                                        : (const float4*)(g_loop + (size_t)(ge - EE) * 32);
            float4 v = p[q];
            int k = q * 4;
            sEA[k + 0][row] = v.x;
            sEA[k + 1][row] = v.y;
            sEA[k + 2][row] = v.z;
            sEA[k + 3][row] = v.w;
        }
    }
    __syncthreads();

    int e0 = base + tid;
    int e1 = base + 128 + tid;
    if (e0 >= EL) return;
    bool has1 = (e1 < EL);

    float hb0[16], hb1[16];
#pragma unroll
    for (int j = 0; j < 16; j++) { hb0[j] = sB1[j]; hb1[j] = sB1[j]; }
#pragma unroll
    for (int k = 0; k < 32; k++) {
        float v0 = sEA[k][tid];
        float v1 = sEA[k][tid + 128];
#pragma unroll
        for (int j = 0; j < 16; j++) {
            float w = sW1[k * 16 + j];
            hb0[j] += v0 * w;
            hb1[j] += v1 * w;
        }
    }
#pragma unroll
    for (int j = 0; j < 16; j++) { hb0[j] = fmaxf(hb0[j], 0.f); hb1[j] = fmaxf(hb1[j], 0.f); }

    float ea0_0 = 0.f, ea0_1 = 0.f, ea0_2 = 0.f, ea0_3 = 0.f;
    float ea1_0 = 0.f, ea1_1 = 0.f, ea1_2 = 0.f, ea1_3 = 0.f;
#pragma unroll
    for (int k = 0; k < 32; k++) {
        float t0 = sB2[k], t1 = sB2[k];
#pragma unroll
        for (int j = 0; j < 16; j++) {
            float w = sW2[j * 32 + k];
            t0 += hb0[j] * w;
            t1 += hb1[j] * w;
        }
        float cw0 = 1.f / (1.f + __expf(-t0));
        float cw1 = 1.f / (1.f + __expf(-t1));
        float w0 = sEA[k][tid] * cw0;
        float w1 = sEA[k][tid + 128] * cw1;
        float ae0 = sAE[k], ae1 = sAE[32 + k], ae2 = sAE[64 + k], ae3 = sAE[96 + k];
        ea0_0 += w0 * ae0; ea0_1 += w0 * ae1; ea0_2 += w0 * ae2; ea0_3 += w0 * ae3;
        ea1_0 += w1 * ae0; ea1_1 += w1 * ae1; ea1_2 += w1 * ae2; ea1_3 += w1 * ae3;
    }

    float* dstp = g_eatt + (size_t)lay * EL * 4;
    *(float4*)(dstp + (size_t)e0 * 4) = make_float4(ea0_0, ea0_1, ea0_2, ea0_3);
    if (has1)
        *(float4*)(dstp + (size_t)e1 * 4) = make_float4(ea1_0, ea1_1, ea1_2, ea1_3);
}

// ---------------- edge_fin: alpha = exp(leaky(ai+aj+eatt)) -> sorted slot -----
__global__ void edge_fin_kernel(const int* __restrict__ src, const int* __restrict__ dst,
                                int heads, int lay,
                                const float* __restrict__ ai, const float* __restrict__ aj) {
    int e = blockIdx.x * blockDim.x + threadIdx.x;
    if (e >= EL) return;
    int s, d;
    if (e < EE) { s = src[e]; d = dst[e]; }
    else        { s = d = e - EE; }
    int pos = g_perm[e];
    const float* ep = g_eatt + (size_t)lay * EL * 4 + (size_t)e * 4;
    if (heads == 4) {
        float4 et  = *(const float4*)ep;
        float4 aid = *(const float4*)(ai + d * 4);
        float4 ajs = *(const float4*)(aj + s * 4);
        float a0 = aid.x + ajs.x + et.x;
        float a1 = aid.y + ajs.y + et.y;
        float a2 = aid.z + ajs.z + et.z;
        float a3 = aid.w + ajs.w + et.w;
        a0 = fminf((a0 > 0.f) ? a0 : 0.2f * a0, 80.f);
        a1 = fminf((a1 > 0.f) ? a1 : 0.2f * a1, 80.f);
        a2 = fminf((a2 > 0.f) ? a2 : 0.2f * a2, 80.f);
        a3 = fminf((a3 > 0.f) ? a3 : 0.2f * a3, 80.f);
        *(float4*)(g_alpha + (size_t)pos * 4) =
            make_float4(__expf(a0), __expf(a1), __expf(a2), __expf(a3));
    } else {
        float a = ai[d] + aj[s] + ep[0];
        a = fminf((a > 0.f) ? a : 0.2f * a, 80.f);
        g_alpha[pos] = __expf(a);
    }
}

// ---------------- fused aggregate + softmax norm + bias (+BN+ELU) -------------
__global__ void agg4_kernel(int lw2, int outdim, int heads, int csh,
                            const float* __restrict__ bias,
                            const float* __restrict__ gamma,
                            const float* __restrict__ beta,
                            const float* __restrict__ mean,
                            const float* __restrict__ var) {
    int gw   = (blockIdx.x * blockDim.x + threadIdx.x) >> 5;
    int lane = threadIdx.x & 31;
    int w    = gw >> lw2;
    if (w >= NN) return;
    int wi   = gw & ((1 << lw2) - 1);
    int col0 = wi * 128 + lane * 4;
    int head = col0 >> csh;

    int p0 = g_rowptr[w], p1 = g_rowptr[w + 1];
    float a0 = 0.f, a1 = 0.f, a2 = 0.f, a3 = 0.f, ss = 0.f;
    const float* hb = g_h + col0;
    for (int p = p0; p < p1; p++) {
        int s = g_col_src[p];
        float wg = g_alpha[p * heads + head];
        ss += wg;
        float4 v = *(const float4*)(hb + (size_t)s * outdim);
        a0 += wg * v.x; a1 += wg * v.y; a2 += wg * v.z; a3 += wg * v.w;
    }
    float r = 1.f / (ss + 1e-16f);
    float v0 = a0 * r + bias[col0 + 0];
    float v1 = a1 * r + bias[col0 + 1];
    float v2 = a2 * r + bias[col0 + 2];
    float v3 = a3 * r + bias[col0 + 3];
    v0 = (v0 - mean[col0 + 0]) * rsqrtf(var[col0 + 0] + 1e-5f) * gamma[col0 + 0] + beta[col0 + 0];
    v1 = (v1 - mean[col0 + 1]) * rsqrtf(var[col0 + 1] + 1e-5f) * gamma[col0 + 1] + beta[col0 + 1];
    v2 = (v2 - mean[col0 + 2]) * rsqrtf(var[col0 + 2] + 1e-5f) * gamma[col0 + 2] + beta[col0 + 2];
    v3 = (v3 - mean[col0 + 3]) * rsqrtf(var[col0 + 3] + 1e-5f) * gamma[col0 + 3] + beta[col0 + 3];
    v0 = (v0 > 0.f) ? v0 : expm1f(v0);
    v1 = (v1 > 0.f) ? v1 : expm1f(v1);
    v2 = (v2 > 0.f) ? v2 : expm1f(v2);
    v3 = (v3 > 0.f) ? v3 : expm1f(v3);
    float4 out = make_float4(v0, v1, v2, v3);
    *(float4*)(g_act + (size_t)w * outdim + col0) = out;
}

__global__ void agg2_kernel(const float* __restrict__ bias, float* __restrict__ outp) {
    int gw   = (blockIdx.x * blockDim.x + threadIdx.x) >> 5;
    int lane = threadIdx.x & 31;
    if (gw >= NN) return;
    int col0 = lane * 2;

    int p0 = g_rowptr[gw], p1 = g_rowptr[gw + 1];
    float a0 = 0.f, a1 = 0.f, ss = 0.f;
    const float* hb = g_h + col0;
    for (int p = p0; p < p1; p++) {
        int s = g_col_src[p];
        float wg = g_alpha[p];
        ss += wg;
        float2 v = *(const float2*)(hb + (size_t)s * 64);
        a0 += wg * v.x; a1 += wg * v.y;
    }
    float r = 1.f / (ss + 1e-16f);
    float2 out = make_float2(a0 * r + bias[col0], a1 * r + bias[col0 + 1]);
    *(float2*)(outp + (size_t)gw * 64 + col0) = out;
}

// ---------------- host --------------------------------------------------------
extern "C" void kernel_launch(void* const* d_in, const int* in_sizes, int n_in,
                              void* d_out, int out_size) {
    const float* x     = (const float*)d_in[0];
    const int*   src   = (const int*)d_in[1];
    const int*   dst   = src + EE;
    const float* eattr = (const float*)d_in[2];

    struct LP {
        const float *W, *ew1, *eb1, *ew2, *eb2, *att, *bias;
        int K, out_c, heads;
        const float *gamma, *beta, *mean, *var;
    };
    LP lp[3];
    lp[0] = { (const float*)d_in[3],  (const float*)d_in[4],  (const float*)d_in[5],
              (const float*)d_in[6],  (const float*)d_in[7],  (const float*)d_in[8],
              (const float*)d_in[9],  128, 64, 4,
              (const float*)d_in[24], (const float*)d_in[25], (const float*)d_in[26], (const float*)d_in[27] };
    lp[1] = { (const float*)d_in[10], (const float*)d_in[11], (const float*)d_in[12],
              (const float*)d_in[13], (const float*)d_in[14], (const float*)d_in[15],
              (const float*)d_in[16], 256, 32, 4,
              (const float*)d_in[28], (const float*)d_in[29], (const float*)d_in[30], (const float*)d_in[31] };
    lp[2] = { (const float*)d_in[17], (const float*)d_in[18], (const float*)d_in[19],
              (const float*)d_in[20], (const float*)d_in[21], (const float*)d_in[22],
              (const float*)d_in[23], 128, 64, 1,
              nullptr, nullptr, nullptr, nullptr };

    static cudaStream_t s2 = nullptr;
    static cudaEvent_t evFork = nullptr, evF[3] = {nullptr, nullptr, nullptr},
                       evA[2] = {nullptr, nullptr};
    if (!s2) {
        cudaStreamCreateWithFlags(&s2, cudaStreamNonBlocking);
        cudaEventCreateWithFlags(&evFork, cudaEventDisableTiming);
        for (int i = 0; i < 3; i++) cudaEventCreateWithFlags(&evF[i], cudaEventDisableTiming);
        for (int i = 0; i < 2; i++) cudaEventCreateWithFlags(&evA[i], cudaEventDisableTiming);
    }

    // device pointers into __device__ globals (host-side arithmetic on symbols
    // is fine because kernels receive them as plain pointers)
    float *aiL[3], *ajL[3];
    for (int L = 0; L < 3; L++) {
        // use a kernel-visible address: pass offsets computed on device symbols
        // via cudaGetSymbolAddress-free trick: g_ai decays in device code only,
        // so pass base offsets through kernel args instead.
        aiL[L] = nullptr; ajL[L] = nullptr; // placeholders (resolved below)
    }
    // Resolve device addresses once
    static float *d_ai = nullptr, *d_aj = nullptr, *d_wtI = nullptr, *d_wtJ = nullptr;
    if (!d_ai) {
        cudaGetSymbolAddress((void**)&d_ai, g_ai);
        cudaGetSymbolAddress((void**)&d_aj, g_aj);
        cudaGetSymbolAddress((void**)&d_wtI, g_wtI);
        cudaGetSymbolAddress((void**)&d_wtJ, g_wtJ);
    }
    for (int L = 0; L < 3; L++) {
        aiL[L] = d_ai + (size_t)L * NN * 4;
        ajL[L] = d_aj + (size_t)L * NN * 4;
    }

    // ---- fork side stream ----
    cudaEventRecord(evFork, 0);
    cudaStreamWaitEvent(s2, evFork, 0);

    initcnt_kernel<<<(NN + 255) / 256, 256, 0, s2>>>();                 // ord 0
    hist_kernel<<<(EE + 255) / 256, 256, 0, s2>>>(dst);                 // ord 1
    scan_kernel<<<1, 1024, 0, s2>>>();                                  // ord 2

    {   // gemm L0 at ordinal 3 (profiled slot)
        dim3 ggrid((NN + 127) / 128, 2);
        gemm128_kernel<<<ggrid, 256>>>(x, 1, lp[0].W, 128, 256);        // ord 3
    }

    scatter_kernel<<<(EL + 255) / 256, 256, 0, s2>>>(src, dst);
    loop_attr_kernel<<<(NN * 32 + 255) / 256, 256, 0, s2>>>(eattr);

    for (int L = 0; L < 3; L++) {
        const LP& p = lp[L];
        int n = p.heads * p.K;
        wt_kernel<<<(n + 255) / 256, 256, 0, s2>>>(p.W, p.att, p.K, p.heads * p.out_c,
                                                   p.out_c, p.heads,
                                                   d_wtI + L * 1024, d_wtJ + L * 1024);
    }

    // L0 side chain: ai gemv (reads x) + edge_pre + fin
    ai4_kernel<<<(NN * 32 + 255) / 256, 256, 0, s2>>>(x, 128, d_wtI, d_wtJ, aiL[0], ajL[0]);
    edge_pre_kernel<<<(EL + 255) / 256, 128, 0, s2>>>(eattr,
        lp[0].ew1, lp[0].eb1, lp[0].ew2, lp[0].eb2, lp[0].att, 4, 64, 0);
    edge_fin_kernel<<<(EL + 255) / 256, 256, 0, s2>>>(src, dst, 4, 0, aiL[0], ajL[0]);
    cudaEventRecord(evF[0], s2);
    edge_pre_kernel<<<(EL + 255) / 256, 128, 0, s2>>>(eattr,
        lp[1].ew1, lp[1].eb1, lp[1].ew2, lp[1].eb2, lp[1].att, 4, 32, 1);
    edge_pre_kernel<<<(EL + 255) / 256, 128, 0, s2>>>(eattr,
        lp[2].ew1, lp[2].eb1, lp[2].ew2, lp[2].eb2, lp[2].att, 1, 64, 2);

    // ---- main chain ----
    cudaStreamWaitEvent(0, evF[0], 0);
    agg4_kernel<<<(NN * 2 + 7) / 8, 256>>>(1, 256, 4, 6,
        lp[0].bias, lp[0].gamma, lp[0].beta, lp[0].mean, lp[0].var);
    cudaEventRecord(evA[0], 0);

    cudaStreamWaitEvent(s2, evA[0], 0);
    ai4_kernel<<<(NN * 32 + 255) / 256, 256, 0, s2>>>(nullptr, 256,
        d_wtI + 1024, d_wtJ + 1024, aiL[1], ajL[1]);          // reads g_act
    edge_fin_kernel<<<(EL + 255) / 256, 256, 0, s2>>>(src, dst, 4, 1, aiL[1], ajL[1]);
    cudaEventRecord(evF[1], s2);

    {
        dim3 ggrid((NN + 127) / 128, 1);
        gemm128_kernel<<<ggrid, 256>>>(x, 0, lp[1].W, 256, 128);
    }
    cudaStreamWaitEvent(0, evF[1], 0);
    agg4_kernel<<<(NN + 7) / 8, 256>>>(0, 128, 4, 5,
        lp[1].bias, lp[1].gamma, lp[1].beta, lp[1].mean, lp[1].var);
    cudaEventRecord(evA[1], 0);

    cudaStreamWaitEvent(s2, evA[1], 0);
    ai1_kernel<<<(NN * 32 + 255) / 256, 256, 0, s2>>>(nullptr, 128,
        d_wtI + 2048, d_wtJ + 2048, aiL[2], ajL[2]);          // reads g_act
    edge_fin_kernel<<<(EL + 255) / 256, 256, 0, s2>>>(src, dst, 1, 2, aiL[2], ajL[2]);
    cudaEventRecord(evF[2], s2);

    {
        dim3 ggrid((NN + 127) / 128, 1);
        gemm64_kernel<<<ggrid, 256>>>(x, 0, lp[2].W, 128, 64);
    }
    cudaStreamWaitEvent(0, evF[2], 0);
    agg2_kernel<<<(NN + 7) / 8, 256>>>(lp[2].bias, (float*)d_out);
}

// round 13
// speedup vs baseline: 1.0024x; 1.0024x over previous
#include <cuda_runtime.h>
#include <math.h>

#define NN 50000
#define EE 400000
#define EL 450000   // E + N self loops
#define ED 32

// ---------------- scratch (static device globals; no allocation) -------------
__device__ float g_h[NN * 256];      // projected features
__device__ float g_act[NN * 256];    // activated layer input (layers 2,3)
__device__ float g_loop[NN * ED];    // loop_attr (segment mean of edge_attr)
__device__ float g_ai[3 * NN * 4];   // per-layer node attention scalars (i)
__device__ float g_aj[3 * NN * 4];
__device__ float g_wtI[2 * 1024];    // L1/L2 projected att vectors (W @ att_i)
__device__ float g_wtJ[2 * 1024];
__device__ float g_alpha[EL * 4];    // exp weights, sorted by dst
__device__ float g_eatt[3 * EL * 4]; // per-layer edge-MLP attention term (by edge id)
__device__ int   g_rowptr[NN + 1];
__device__ int   g_cnt[NN];
__device__ int   g_col_src[EL];
__device__ int   g_col_eid[EL];
__device__ int   g_perm[EL];

// ---------------- CSR build ----------------------------------------------------
__global__ void initcnt_kernel() {
    int i = blockIdx.x * blockDim.x + threadIdx.x;
    if (i < NN) g_cnt[i] = 1;        // self loop
}

__global__ void hist_kernel(const int* __restrict__ dst) {
    int e = blockIdx.x * blockDim.x + threadIdx.x;
    if (e < EE) atomicAdd(&g_cnt[dst[e]], 1);
}

__global__ void scan_kernel() {
    __shared__ int sb[1024];
    int t = threadIdx.x;
    const int CH = (NN + 1023) / 1024;
    int lo = t * CH;
    int hi = min(lo + CH, NN);
    int s = 0;
    for (int i = lo; i < hi; i++) s += g_cnt[i];
    sb[t] = s;
    __syncthreads();
    for (int off = 1; off < 1024; off <<= 1) {
        int v = (t >= off) ? sb[t - off] : 0;
        __syncthreads();
        sb[t] += v;
        __syncthreads();
    }
    int run = (t > 0) ? sb[t - 1] : 0;
    for (int i = lo; i < hi; i++) {
        g_rowptr[i] = run;
        run += g_cnt[i];
        g_cnt[i] = 0;
    }
    if (t == 0) g_rowptr[NN] = EL;
}

__global__ void scatter_kernel(const int* __restrict__ src, const int* __restrict__ dst) {
    int e = blockIdx.x * blockDim.x + threadIdx.x;
    if (e >= EL) return;
    int s, d;
    if (e < EE) { s = src[e]; d = dst[e]; }
    else        { s = d = e - EE; }
    int pos = g_rowptr[d] + atomicAdd(&g_cnt[d], 1);
    g_col_src[pos] = s;
    g_col_eid[pos] = e;
    g_perm[e] = pos;
}

__global__ void loop_attr_kernel(const float* __restrict__ ea) {
    int w = (blockIdx.x * blockDim.x + threadIdx.x) >> 5;
    int lane = threadIdx.x & 31;
    if (w >= NN) return;
    int p0 = g_rowptr[w], p1 = g_rowptr[w + 1];
    float s = 0.f;
    int c = 0;
    for (int p = p0; p < p1; p++) {
        int eid = g_col_eid[p];
        if (eid < EE) { s += ea[(size_t)eid * ED + lane]; c++; }
    }
    g_loop[w * ED + lane] = (c > 0) ? s / (float)c : 0.f;
}

// ---------------- wtilde: w̃[h,k] = sum_c W[k, h*out_c+c] * att_{i/j}[h,c] ------
__global__ void wt_kernel(const float* __restrict__ W, const float* __restrict__ att,
                          int K, int Nout, int out_c, int heads,
                          float* __restrict__ wtI, float* __restrict__ wtJ) {
    int t = blockIdx.x * blockDim.x + threadIdx.x;
    if (t >= heads * K) return;
    int h = t / K, k = t - h * K;
    int stride = 2 * out_c + ED;
    const float* Wr  = W + (size_t)k * Nout + h * out_c;
    const float* ati = att + h * stride;
    const float* atj = ati + out_c;
    float si = 0.f, sj = 0.f;
    for (int c = 0; c < out_c; c++) {
        float w = Wr[c];
        si += w * ati[c];
        sj += w * atj[c];
    }
    wtI[t] = si;
    wtJ[t] = sj;
}

// ---------------- ai GEMV over g_act: a[n,h] = dot(act[n,:], w̃[h,:]) ----------
__global__ void ai4_kernel(int K, const float* __restrict__ wtI,
                           const float* __restrict__ wtJ,
                           float* __restrict__ ai, float* __restrict__ aj) {
    __shared__ float sI[1024], sJ[1024];
    int tid = threadIdx.x;
    for (int i = tid; i < 4 * K; i += 256) { sI[i] = wtI[i]; sJ[i] = wtJ[i]; }
    __syncthreads();
    int gw = (blockIdx.x * blockDim.x + tid) >> 5;
    int lane = tid & 31;
    if (gw >= NN) return;
    const float* Ap = g_act + (size_t)gw * K;
    float i0 = 0.f, i1 = 0.f, i2 = 0.f, i3 = 0.f;
    float j0 = 0.f, j1 = 0.f, j2 = 0.f, j3 = 0.f;
    for (int k = lane; k < K; k += 32) {
        float v = Ap[k];
        i0 += v * sI[k];         i1 += v * sI[K + k];
        i2 += v * sI[2 * K + k]; i3 += v * sI[3 * K + k];
        j0 += v * sJ[k];         j1 += v * sJ[K + k];
        j2 += v * sJ[2 * K + k]; j3 += v * sJ[3 * K + k];
    }
#pragma unroll
    for (int o = 16; o > 0; o >>= 1) {
        i0 += __shfl_xor_sync(0xffffffffu, i0, o);
        i1 += __shfl_xor_sync(0xffffffffu, i1, o);
        i2 += __shfl_xor_sync(0xffffffffu, i2, o);
        i3 += __shfl_xor_sync(0xffffffffu, i3, o);
        j0 += __shfl_xor_sync(0xffffffffu, j0, o);
        j1 += __shfl_xor_sync(0xffffffffu, j1, o);
        j2 += __shfl_xor_sync(0xffffffffu, j2, o);
        j3 += __shfl_xor_sync(0xffffffffu, j3, o);
    }
    if (lane == 0) {
        *(float4*)(ai + (size_t)gw * 4) = make_float4(i0, i1, i2, i3);
        *(float4*)(aj + (size_t)gw * 4) = make_float4(j0, j1, j2, j3);
    }
}

__global__ void ai1_kernel(int K, const float* __restrict__ wtI,
                           const float* __restrict__ wtJ,
                           float* __restrict__ ai, float* __restrict__ aj) {
    __shared__ float sI[256], sJ[256];
    int tid = threadIdx.x;
    for (int i = tid; i < K; i += 256) { sI[i] = wtI[i]; sJ[i] = wtJ[i]; }
    __syncthreads();
    int gw = (blockIdx.x * blockDim.x + tid) >> 5;
    int lane = tid & 31;
    if (gw >= NN) return;
    const float* Ap = g_act + (size_t)gw * K;
    float i0 = 0.f, j0 = 0.f;
    for (int k = lane; k < K; k += 32) {
        float v = Ap[k];
        i0 += v * sI[k];
        j0 += v * sJ[k];
    }
#pragma unroll
    for (int o = 16; o > 0; o >>= 1) {
        i0 += __shfl_xor_sync(0xffffffffu, i0, o);
        j0 += __shfl_xor_sync(0xffffffffu, j0, o);
    }
    if (lane == 0) { ai[gw] = i0; aj[gw] = j0; }
}

// ---------------- GEMM A: 128x128x8 tile, 8x8 micro-tile (R10-proven) ---------
__global__ void gemm128_kernel(const float* __restrict__ x_ext, int use_ext,
                               const float* __restrict__ W, int K, int Nout) {
    __shared__ float As[2][8][132];
    __shared__ float Bs[2][8][128];
    const float* A = use_ext ? x_ext : g_act;
    int t = threadIdx.x;
    int tx = t & 15;
    int ty = t >> 4;
    int row0 = blockIdx.x * 128, col0 = blockIdx.y * 128;

    int ar = t >> 1, ak = (t & 1) * 4;
    int arow = min(row0 + ar, NN - 1);
    const float* Ap = A + (size_t)arow * K + ak;
    int br = t >> 5, bc = (t & 31) * 4;
    const float* Wp = W + (size_t)br * Nout + col0 + bc;

    int ktiles = K >> 3;
    float4 pa = *(const float4*)(Ap);
    float4 pb = *(const float4*)(Wp);

    float acc[8][8];
#pragma unroll
    for (int i = 0; i < 8; i++)
#pragma unroll
        for (int j = 0; j < 8; j++) acc[i][j] = 0.f;

    for (int kt = 0; kt < ktiles; kt++) {
        int cbuf = kt & 1;
        As[cbuf][ak + 0][ar] = pa.x;
        As[cbuf][ak + 1][ar] = pa.y;
        As[cbuf][ak + 2][ar] = pa.z;
        As[cbuf][ak + 3][ar] = pa.w;
        *(float4*)&Bs[cbuf][br][bc] = pb;
        __syncthreads();

        if (kt + 1 < ktiles) {
            int k0 = (kt + 1) << 3;
            pa = *(const float4*)(Ap + k0);
            pb = *(const float4*)(Wp + (size_t)k0 * Nout);
        }

#pragma unroll
        for (int kk = 0; kk < 8; kk++) {
            float4 a0 = *(const float4*)&As[cbuf][kk][ty * 8];
            float4 a1 = *(const float4*)&As[cbuf][kk][ty * 8 + 4];
            float4 b0 = *(const float4*)&Bs[cbuf][kk][tx * 8];
            float4 b1 = *(const float4*)&Bs[cbuf][kk][tx * 8 + 4];
            acc[0][0] += a0.x * b0.x; acc[0][1] += a0.x * b0.y; acc[0][2] += a0.x * b0.z; acc[0][3] += a0.x * b0.w;
            acc[0][4] += a0.x * b1.x; acc[0][5] += a0.x * b1.y; acc[0][6] += a0.x * b1.z; acc[0][7] += a0.x * b1.w;
            acc[1][0] += a0.y * b0.x; acc[1][1] += a0.y * b0.y; acc[1][2] += a0.y * b0.z; acc[1][3] += a0.y * b0.w;
            acc[1][4] += a0.y * b1.x; acc[1][5] += a0.y * b1.y; acc[1][6] += a0.y * b1.z; acc[1][7] += a0.y * b1.w;
            acc[2][0] += a0.z * b0.x; acc[2][1] += a0.z * b0.y; acc[2][2] += a0.z * b0.z; acc[2][3] += a0.z * b0.w;
            acc[2][4] += a0.z * b1.x; acc[2][5] += a0.z * b1.y; acc[2][6] += a0.z * b1.z; acc[2][7] += a0.z * b1.w;
            acc[3][0] += a0.w * b0.x; acc[3][1] += a0.w * b0.y; acc[3][2] += a0.w * b0.z; acc[3][3] += a0.w * b0.w;
            acc[3][4] += a0.w * b1.x; acc[3][5] += a0.w * b1.y; acc[3][6] += a0.w * b1.z; acc[3][7] += a0.w * b1.w;
            acc[4][0] += a1.x * b0.x; acc[4][1] += a1.x * b0.y; acc[4][2] += a1.x * b0.z; acc[4][3] += a1.x * b0.w;
            acc[4][4] += a1.x * b1.x; acc[4][5] += a1.x * b1.y; acc[4][6] += a1.x * b1.z; acc[4][7] += a1.x * b1.w;
            acc[5][0] += a1.y * b0.x; acc[5][1] += a1.y * b0.y; acc[5][2] += a1.y * b0.z; acc[5][3] += a1.y * b0.w;
            acc[5][4] += a1.y * b1.x; acc[5][5] += a1.y * b1.y; acc[5][6] += a1.y * b1.z; acc[5][7] += a1.y * b1.w;
            acc[6][0] += a1.z * b0.x; acc[6][1] += a1.z * b0.y; acc[6][2] += a1.z * b0.z; acc[6][3] += a1.z * b0.w;
            acc[6][4] += a1.z * b1.x; acc[6][5] += a1.z * b1.y; acc[6][6] += a1.z * b1.z; acc[6][7] += a1.z * b1.w;
            acc[7][0] += a1.w * b0.x; acc[7][1] += a1.w * b0.y; acc[7][2] += a1.w * b0.z; acc[7][3] += a1.w * b0.w;
            acc[7][4] += a1.w * b1.x; acc[7][5] += a1.w * b1.y; acc[7][6] += a1.w * b1.z; acc[7][7] += a1.w * b1.w;
        }
        __syncthreads();
    }

    int gcol = col0 + tx * 8;
#pragma unroll
    for (int i = 0; i < 8; i++) {
        int gr = row0 + ty * 8 + i;
        if (gr < NN) {
            *(float4*)&g_h[(size_t)gr * Nout + gcol]     = make_float4(acc[i][0], acc[i][1], acc[i][2], acc[i][3]);
            *(float4*)&g_h[(size_t)gr * Nout + gcol + 4] = make_float4(acc[i][4], acc[i][5], acc[i][6], acc[i][7]);
        }
    }
}

// ---------------- GEMM B: 128x64x16 tile, 8x4 micro-tile (R10-proven) ---------
__global__ void gemm64_kernel(const float* __restrict__ x_ext, int use_ext,
                              const float* __restrict__ W, int K, int Nout) {
    __shared__ float As[2][16][132];
    __shared__ float Bs[2][16][64];
    const float* A = use_ext ? x_ext : g_act;
    int t = threadIdx.x;
    int tx = t & 15;
    int ty = t >> 4;
    int row0 = blockIdx.x * 128, col0 = blockIdx.y * 64;

    int ar0 = t >> 2, ak = (t & 3) * 4;
    int arowA = min(row0 + ar0,      NN - 1);
    int arowB = min(row0 + ar0 + 64, NN - 1);
    const float* ApA = A + (size_t)arowA * K + ak;
    const float* ApB = A + (size_t)arowB * K + ak;
    int br = t >> 4, bc = (t & 15) * 4;
    const float* Wp = W + (size_t)br * Nout + col0 + bc;

    int ktiles = K >> 4;
    float4 pa0 = *(const float4*)(ApA);
    float4 pa1 = *(const float4*)(ApB);
    float4 pb  = *(const float4*)(Wp);

    float acc[8][4];
#pragma unroll
    for (int i = 0; i < 8; i++)
#pragma unroll
        for (int j = 0; j < 4; j++) acc[i][j] = 0.f;

    for (int kt = 0; kt < ktiles; kt++) {
        int cbuf = kt & 1;
        As[cbuf][ak + 0][ar0] = pa0.x;  As[cbuf][ak + 1][ar0] = pa0.y;
        As[cbuf][ak + 2][ar0] = pa0.z;  As[cbuf][ak + 3][ar0] = pa0.w;
        As[cbuf][ak + 0][ar0 + 64] = pa1.x;  As[cbuf][ak + 1][ar0 + 64] = pa1.y;
        As[cbuf][ak + 2][ar0 + 64] = pa1.z;  As[cbuf][ak + 3][ar0 + 64] = pa1.w;
        *(float4*)&Bs[cbuf][br][bc] = pb;
        __syncthreads();

        if (kt + 1 < ktiles) {
            int k0 = (kt + 1) << 4;
            pa0 = *(const float4*)(ApA + k0);
            pa1 = *(const float4*)(ApB + k0);
            pb  = *(const float4*)(Wp + (size_t)k0 * Nout);
        }

#pragma unroll
        for (int kk = 0; kk < 16; kk++) {
            float4 a0 = *(const float4*)&As[cbuf][kk][ty * 8];
            float4 a1 = *(const float4*)&As[cbuf][kk][ty * 8 + 4];
            float4 b  = *(const float4*)&Bs[cbuf][kk][tx * 4];
            acc[0][0] += a0.x * b.x; acc[0][1] += a0.x * b.y; acc[0][2] += a0.x * b.z; acc[0][3] += a0.x * b.w;
            acc[1][0] += a0.y * b.x; acc[1][1] += a0.y * b.y; acc[1][2] += a0.y * b.z; acc[1][3] += a0.y * b.w;
            acc[2][0] += a0.z * b.x; acc[2][1] += a0.z * b.y; acc[2][2] += a0.z * b.z; acc[2][3] += a0.z * b.w;
            acc[3][0] += a0.w * b.x; acc[3][1] += a0.w * b.y; acc[3][2] += a0.w * b.z; acc[3][3] += a0.w * b.w;
            acc[4][0] += a1.x * b.x; acc[4][1] += a1.x * b.y; acc[4][2] += a1.x * b.z; acc[4][3] += a1.x * b.w;
            acc[5][0] += a1.y * b.x; acc[5][1] += a1.y * b.y; acc[5][2] += a1.y * b.z; acc[5][3] += a1.y * b.w;
            acc[6][0] += a1.z * b.x; acc[6][1] += a1.z * b.y; acc[6][2] += a1.z * b.z; acc[6][3] += a1.z * b.w;
            acc[7][0] += a1.w * b.x; acc[7][1] += a1.w * b.y; acc[7][2] += a1.w * b.z; acc[7][3] += a1.w * b.w;
        }
        __syncthreads();
    }

    int gcol = col0 + tx * 4;
#pragma unroll
    for (int i = 0; i < 8; i++) {
        int gr = row0 + ty * 8 + i;
        if (gr < NN)
            *(float4*)&g_h[(size_t)gr * Nout + gcol] =
                make_float4(acc[i][0], acc[i][1], acc[i][2], acc[i][3]);
    }
}

// ---------------- per-node attention scalars (L0 only, reads g_h) -------------
__global__ void att_node_kernel(const float* __restrict__ att, int heads, int out_c,
                                float* __restrict__ ai, float* __restrict__ aj) {
    int gw   = (blockIdx.x * blockDim.x + threadIdx.x) >> 5;
    int lane = threadIdx.x & 31;
    if (gw >= NN * heads) return;
    int n = gw / heads, hh = gw - n * heads;
    int hd = heads * out_c;
    int stride = 2 * out_c + ED;
    const float* hp = g_h + (size_t)n * hd + hh * out_c;
    const float* aip = att + hh * stride;
    const float* ajp = aip + out_c;
    float si = 0.f, sj = 0.f;
    for (int j = lane; j < out_c; j += 32) {
        float v = hp[j];
        si += v * aip[j];
        sj += v * ajp[j];
    }
#pragma unroll
    for (int o = 16; o > 0; o >>= 1) {
        si += __shfl_xor_sync(0xffffffffu, si, o);
        sj += __shfl_xor_sync(0xffffffffu, sj, o);
    }
    if (lane == 0) { ai[gw] = si; aj[gw] = sj; }
}

// ---------------- edge_pre: gating MLP -> g_eatt (h-independent) --------------
__global__ void edge_pre_kernel(const float* __restrict__ eattr,
                                const float* __restrict__ ew1, const float* __restrict__ eb1,
                                const float* __restrict__ ew2, const float* __restrict__ eb2,
                                const float* __restrict__ att,
                                int heads, int out_c, int lay) {
    __shared__ float sEA[32][260];
    __shared__ float sW1[32 * 16], sB1[16], sW2[16 * 32], sB2[32], sAE[4 * 32];
    int tid = threadIdx.x;
    int base = blockIdx.x * 256;
    int stride = 2 * out_c + ED;

    for (int i = tid; i < 512; i += 128) { sW1[i] = ew1[i]; sW2[i] = ew2[i]; }
    if (tid < 16) sB1[tid] = eb1[tid];
    if (tid < 32) sB2[tid] = eb2[tid];
    for (int i = tid; i < heads * 32; i += 128) {
        int h = i >> 5, k = i & 31;
        sAE[i] = att[h * stride + 2 * out_c + k];
    }
    for (int i = tid; i < 256 * 8; i += 128) {
        int row = i >> 3, q = i & 7;
        int ge = base + row;
        if (ge < EL) {
            const float4* p = (ge < EE) ? (const float4*)(eattr + (size_t)ge * 32)
                                        : (const float4*)(g_loop + (size_t)(ge - EE) * 32);
            float4 v = p[q];
            int k = q * 4;
            sEA[k + 0][row] = v.x;
            sEA[k + 1][row] = v.y;
            sEA[k + 2][row] = v.z;
            sEA[k + 3][row] = v.w;
        }
    }
    __syncthreads();

    int e0 = base + tid;
    int e1 = base + 128 + tid;
    if (e0 >= EL) return;
    bool has1 = (e1 < EL);

    float hb0[16], hb1[16];
#pragma unroll
    for (int j = 0; j < 16; j++) { hb0[j] = sB1[j]; hb1[j] = sB1[j]; }
#pragma unroll
    for (int k = 0; k < 32; k++) {
        float v0 = sEA[k][tid];
        float v1 = sEA[k][tid + 128];
#pragma unroll
        for (int j = 0; j < 16; j++) {
            float w = sW1[k * 16 + j];
            hb0[j] += v0 * w;
            hb1[j] += v1 * w;
        }
    }
#pragma unroll
    for (int j = 0; j < 16; j++) { hb0[j] = fmaxf(hb0[j], 0.f); hb1[j] = fmaxf(hb1[j], 0.f); }

    float ea0_0 = 0.f, ea0_1 = 0.f, ea0_2 = 0.f, ea0_3 = 0.f;
    float ea1_0 = 0.f, ea1_1 = 0.f, ea1_2 = 0.f, ea1_3 = 0.f;
#pragma unroll
    for (int k = 0; k < 32; k++) {
        float t0 = sB2[k], t1 = sB2[k];
#pragma unroll
        for (int j = 0; j < 16; j++) {
            float w = sW2[j * 32 + k];
            t0 += hb0[j] * w;
            t1 += hb1[j] * w;
        }
        float cw0 = 1.f / (1.f + __expf(-t0));
        float cw1 = 1.f / (1.f + __expf(-t1));
        float w0 = sEA[k][tid] * cw0;
        float w1 = sEA[k][tid + 128] * cw1;
        float ae0 = sAE[k], ae1 = sAE[32 + k], ae2 = sAE[64 + k], ae3 = sAE[96 + k];
        ea0_0 += w0 * ae0; ea0_1 += w0 * ae1; ea0_2 += w0 * ae2; ea0_3 += w0 * ae3;
        ea1_0 += w1 * ae0; ea1_1 += w1 * ae1; ea1_2 += w1 * ae2; ea1_3 += w1 * ae3;
    }

    float* dstp = g_eatt + (size_t)lay * EL * 4;
    *(float4*)(dstp + (size_t)e0 * 4) = make_float4(ea0_0, ea0_1, ea0_2, ea0_3);
    if (has1)
        *(float4*)(dstp + (size_t)e1 * 4) = make_float4(ea1_0, ea1_1, ea1_2, ea1_3);
}

// ---------------- edge_fin: alpha = exp(leaky(ai+aj+eatt)) -> sorted slot -----
__global__ void edge_fin_kernel(const int* __restrict__ src, const int* __restrict__ dst,
                                int heads, int lay,
                                const float* __restrict__ ai, const float* __restrict__ aj) {
    int e = blockIdx.x * blockDim.x + threadIdx.x;
    if (e >= EL) return;
    int s, d;
    if (e < EE) { s = src[e]; d = dst[e]; }
    else        { s = d = e - EE; }
    int pos = g_perm[e];
    const float* ep = g_eatt + (size_t)lay * EL * 4 + (size_t)e * 4;
    if (heads == 4) {
        float4 et  = *(const float4*)ep;
        float4 aid = *(const float4*)(ai + d * 4);
        float4 ajs = *(const float4*)(aj + s * 4);
        float a0 = aid.x + ajs.x + et.x;
        float a1 = aid.y + ajs.y + et.y;
        float a2 = aid.z + ajs.z + et.z;
        float a3 = aid.w + ajs.w + et.w;
        a0 = fminf((a0 > 0.f) ? a0 : 0.2f * a0, 80.f);
        a1 = fminf((a1 > 0.f) ? a1 : 0.2f * a1, 80.f);
        a2 = fminf((a2 > 0.f) ? a2 : 0.2f * a2, 80.f);
        a3 = fminf((a3 > 0.f) ? a3 : 0.2f * a3, 80.f);
        *(float4*)(g_alpha + (size_t)pos * 4) =
            make_float4(__expf(a0), __expf(a1), __expf(a2), __expf(a3));
    } else {
        float a = ai[d] + aj[s] + ep[0];
        a = fminf((a > 0.f) ? a : 0.2f * a, 80.f);
        g_alpha[pos] = __expf(a);
    }
}

// ---------------- fused aggregate (prefetch-pipelined) ------------------------
__global__ void agg4_kernel(int lw2, int outdim, int heads, int csh,
                            const float* __restrict__ bias,
                            const float* __restrict__ gamma,
                            const float* __restrict__ beta,
                            const float* __restrict__ mean,
                            const float* __restrict__ var) {
    int gw   = (blockIdx.x * blockDim.x + threadIdx.x) >> 5;
    int lane = threadIdx.x & 31;
    int w    = gw >> lw2;
    if (w >= NN) return;
    int wi   = gw & ((1 << lw2) - 1);
    int col0 = wi * 128 + lane * 4;
    int head = col0 >> csh;

    int p0 = g_rowptr[w], p1 = g_rowptr[w + 1];
    float a0 = 0.f, a1 = 0.f, a2 = 0.f, a3 = 0.f, ss = 0.f;
    const float* hb = g_h + col0;

    int   sN = g_col_src[p0];
    float wN = g_alpha[p0 * heads + head];
    for (int p = p0; p < p1; p++) {
        int   s  = sN;
        float wg = wN;
        if (p + 1 < p1) {
            sN = g_col_src[p + 1];
            wN = g_alpha[(p + 1) * heads + head];
        }
        ss += wg;
        float4 v = *(const float4*)(hb + (size_t)s * outdim);
        a0 += wg * v.x; a1 += wg * v.y; a2 += wg * v.z; a3 += wg * v.w;
    }
    float r = 1.f / (ss + 1e-16f);
    float v0 = a0 * r + bias[col0 + 0];
    float v1 = a1 * r + bias[col0 + 1];
    float v2 = a2 * r + bias[col0 + 2];
    float v3 = a3 * r + bias[col0 + 3];
    v0 = (v0 - mean[col0 + 0]) * rsqrtf(var[col0 + 0] + 1e-5f) * gamma[col0 + 0] + beta[col0 + 0];
    v1 = (v1 - mean[col0 + 1]) * rsqrtf(var[col0 + 1] + 1e-5f) * gamma[col0 + 1] + beta[col0 + 1];
    v2 = (v2 - mean[col0 + 2]) * rsqrtf(var[col0 + 2] + 1e-5f) * gamma[col0 + 2] + beta[col0 + 2];
    v3 = (v3 - mean[col0 + 3]) * rsqrtf(var[col0 + 3] + 1e-5f) * gamma[col0 + 3] + beta[col0 + 3];
    v0 = (v0 > 0.f) ? v0 : expm1f(v0);
    v1 = (v1 > 0.f) ? v1 : expm1f(v1);
    v2 = (v2 > 0.f) ? v2 : expm1f(v2);
    v3 = (v3 > 0.f) ? v3 : expm1f(v3);
    float4 out = make_float4(v0, v1, v2, v3);
    *(float4*)(g_act + (size_t)w * outdim + col0) = out;
}

__global__ void agg2_kernel(const float* __restrict__ bias, float* __restrict__ outp) {
    int gw   = (blockIdx.x * blockDim.x + threadIdx.x) >> 5;
    int lane = threadIdx.x & 31;
    if (gw >= NN) return;
    int col0 = lane * 2;

    int p0 = g_rowptr[gw], p1 = g_rowptr[gw + 1];
    float a0 = 0.f, a1 = 0.f, ss = 0.f;
    const float* hb = g_h + col0;

    int   sN = g_col_src[p0];
    float wN = g_alpha[p0];
    for (int p = p0; p < p1; p++) {
        int   s  = sN;
        float wg = wN;
        if (p + 1 < p1) {
            sN = g_col_src[p + 1];
            wN = g_alpha[p + 1];
        }
        ss += wg;
        float2 v = *(const float2*)(hb + (size_t)s * 64);
        a0 += wg * v.x; a1 += wg * v.y;
    }
    float r = 1.f / (ss + 1e-16f);
    float2 out = make_float2(a0 * r + bias[col0], a1 * r + bias[col0 + 1]);
    *(float2*)(outp + (size_t)gw * 64 + col0) = out;
}

// ---------------- host --------------------------------------------------------
extern "C" void kernel_launch(void* const* d_in, const int* in_sizes, int n_in,
                              void* d_out, int out_size) {
    const float* x     = (const float*)d_in[0];
    const int*   src   = (const int*)d_in[1];
    const int*   dst   = src + EE;
    const float* eattr = (const float*)d_in[2];

    struct LP {
        const float *W, *ew1, *eb1, *ew2, *eb2, *att, *bias;
        int K, out_c, heads;
        const float *gamma, *beta, *mean, *var;
    };
    LP lp[3];
    lp[0] = { (const float*)d_in[3],  (const float*)d_in[4],  (const float*)d_in[5],
              (const float*)d_in[6],  (const float*)d_in[7],  (const float*)d_in[8],
              (const float*)d_in[9],  128, 64, 4,
              (const float*)d_in[24], (const float*)d_in[25], (const float*)d_in[26], (const float*)d_in[27] };
    lp[1] = { (const float*)d_in[10], (const float*)d_in[11], (const float*)d_in[12],
              (const float*)d_in[13], (const float*)d_in[14], (const float*)d_in[15],
              (const float*)d_in[16], 256, 32, 4,
              (const float*)d_in[28], (const float*)d_in[29], (const float*)d_in[30], (const float*)d_in[31] };
    lp[2] = { (const float*)d_in[17], (const float*)d_in[18], (const float*)d_in[19],
              (const float*)d_in[20], (const float*)d_in[21], (const float*)d_in[22],
              (const float*)d_in[23], 128, 64, 1,
              nullptr, nullptr, nullptr, nullptr };

    static cudaStream_t s2 = nullptr;
    static cudaEvent_t evFork = nullptr, evE0 = nullptr,
                       evF1 = nullptr, evF2 = nullptr,
                       evA0 = nullptr, evA1 = nullptr;
    if (!s2) {
        cudaStreamCreateWithFlags(&s2, cudaStreamNonBlocking);
        cudaEventCreateWithFlags(&evFork, cudaEventDisableTiming);
        cudaEventCreateWithFlags(&evE0, cudaEventDisableTiming);
        cudaEventCreateWithFlags(&evF1, cudaEventDisableTiming);
        cudaEventCreateWithFlags(&evF2, cudaEventDisableTiming);
        cudaEventCreateWithFlags(&evA0, cudaEventDisableTiming);
        cudaEventCreateWithFlags(&evA1, cudaEventDisableTiming);
    }

    static float *d_ai = nullptr, *d_aj = nullptr, *d_wtI = nullptr, *d_wtJ = nullptr;
    if (!d_ai) {
        cudaGetSymbolAddress((void**)&d_ai, g_ai);
        cudaGetSymbolAddress((void**)&d_aj, g_aj);
        cudaGetSymbolAddress((void**)&d_wtI, g_wtI);
        cudaGetSymbolAddress((void**)&d_wtJ, g_wtJ);
    }
    float* aiL[3] = { d_ai, d_ai + (size_t)NN * 4, d_ai + (size_t)2 * NN * 4 };
    float* ajL[3] = { d_aj, d_aj + (size_t)NN * 4, d_aj + (size_t)2 * NN * 4 };

    // ---- fork side stream: CSR + loop_attr + edge_pre (R10 balance) ----
    cudaEventRecord(evFork, 0);
    cudaStreamWaitEvent(s2, evFork, 0);

    initcnt_kernel<<<(NN + 255) / 256, 256, 0, s2>>>();                 // ord 0
    hist_kernel<<<(EE + 255) / 256, 256, 0, s2>>>(dst);                 // ord 1
    scan_kernel<<<1, 1024, 0, s2>>>();                                  // ord 2

    {   // gemm L0 at ordinal 3 (profiled slot)
        dim3 ggrid((NN + 127) / 128, 2);
        gemm128_kernel<<<ggrid, 256>>>(x, 1, lp[0].W, 128, 256);        // ord 3
    }

    scatter_kernel<<<(EL + 255) / 256, 256, 0, s2>>>(src, dst);
    loop_attr_kernel<<<(NN * 32 + 255) / 256, 256, 0, s2>>>(eattr);

    edge_pre_kernel<<<(EL + 255) / 256, 128, 0, s2>>>(eattr,
        lp[0].ew1, lp[0].eb1, lp[0].ew2, lp[0].eb2, lp[0].att, 4, 64, 0);
    cudaEventRecord(evE0, s2);
    // w̃ for L1/L2 + their edge_pre (fill side-stream slack)
    wt_kernel<<<4, 256, 0, s2>>>(lp[1].W, lp[1].att, 256, 128, 32, 4, d_wtI, d_wtJ);
    wt_kernel<<<1, 256, 0, s2>>>(lp[2].W, lp[2].att, 128, 64, 64, 1, d_wtI + 1024, d_wtJ + 1024);
    edge_pre_kernel<<<(EL + 255) / 256, 128, 0, s2>>>(eattr,
        lp[1].ew1, lp[1].eb1, lp[1].ew2, lp[1].eb2, lp[1].att, 4, 32, 1);
    edge_pre_kernel<<<(EL + 255) / 256, 128, 0, s2>>>(eattr,
        lp[2].ew1, lp[2].eb1, lp[2].ew2, lp[2].eb2, lp[2].att, 1, 64, 2);

    // ---- L0 (main, as R10): att -> fin -> agg ----
    att_node_kernel<<<(NN * 4 * 32 + 255) / 256, 256>>>(lp[0].att, 4, 64, aiL[0], ajL[0]);
    cudaStreamWaitEvent(0, evE0, 0);
    edge_fin_kernel<<<(EL + 255) / 256, 256>>>(src, dst, 4, 0, aiL[0], ajL[0]);
    agg4_kernel<<<(NN * 2 + 7) / 8, 256>>>(1, 256, 4, 6,
        lp[0].bias, lp[0].gamma, lp[0].beta, lp[0].mean, lp[0].var);
    cudaEventRecord(evA0, 0);

    // ---- L1: side = ai_gemv(g_act) + fin (concurrent with main gemm) ----
    cudaStreamWaitEvent(s2, evA0, 0);
    ai4_kernel<<<(NN * 32 + 255) / 256, 256, 0, s2>>>(256, d_wtI, d_wtJ, aiL[1], ajL[1]);
    edge_fin_kernel<<<(EL + 255) / 256, 256, 0, s2>>>(src, dst, 4, 1, aiL[1], ajL[1]);
    cudaEventRecord(evF1, s2);

    {
        dim3 ggrid((NN + 127) / 128, 1);
        gemm128_kernel<<<ggrid, 256>>>(x, 0, lp[1].W, 256, 128);
    }
    cudaStreamWaitEvent(0, evF1, 0);
    agg4_kernel<<<(NN + 7) / 8, 256>>>(0, 128, 4, 5,
        lp[1].bias, lp[1].gamma, lp[1].beta, lp[1].mean, lp[1].var);
    cudaEventRecord(evA1, 0);

    // ---- L2: side = ai_gemv(g_act) + fin (concurrent with main gemm) ----
    cudaStreamWaitEvent(s2, evA1, 0);
    ai1_kernel<<<(NN * 32 + 255) / 256, 256, 0, s2>>>(128, d_wtI + 1024, d_wtJ + 1024,
                                                      aiL[2], ajL[2]);
    edge_fin_kernel<<<(EL + 255) / 256, 256, 0, s2>>>(src, dst, 1, 2, aiL[2], ajL[2]);
    cudaEventRecord(evF2, s2);

    {
        dim3 ggrid((NN + 127) / 128, 1);
        gemm64_kernel<<<ggrid, 256>>>(x, 0, lp[2].W, 128, 64);
    }
    cudaStreamWaitEvent(0, evF2, 0);
    agg2_kernel<<<(NN + 7) / 8, 256>>>(lp[2].bias, (float*)d_out);
}

// round 14
// speedup vs baseline: 1.0809x; 1.0784x over previous
#include <cuda_runtime.h>
#include <math.h>

#define NN 50000
#define EE 400000
#define EL 450000   // E + N self loops
#define ED 32

// ---------------- scratch (static device globals; no allocation) -------------
__device__ float g_h[NN * 256];      // projected features
__device__ float g_act[NN * 256];    // activated layer input (layers 2,3)
__device__ float g_loop[NN * ED];    // loop_attr (segment mean of edge_attr)
__device__ float g_ai[NN * 4];
__device__ float g_aj[NN * 4];
__device__ float g_alpha[EL * 4];    // exp weights, sorted by dst
__device__ float g_eatt[3 * EL * 4]; // per-layer edge-MLP attention term (by edge id)
__device__ int   g_rowptr[NN + 1];
__device__ int   g_cnt[NN];
__device__ int   g_col_src[EL];      // src node per sorted edge
__device__ int   g_col_eid[EL];      // original edge id per sorted edge
__device__ int   g_perm[EL];         // original edge -> sorted position

// ---------------- CSR build (scalar-only kernels) -----------------------------
__global__ void initcnt_kernel() {
    int i = blockIdx.x * blockDim.x + threadIdx.x;
    if (i < NN) g_cnt[i] = 1;        // self loop
}

__global__ void hist_kernel(const int* __restrict__ dst) {
    int e = blockIdx.x * blockDim.x + threadIdx.x;
    if (e < EE) atomicAdd(&g_cnt[dst[e]], 1);
}

__global__ void scan_kernel() {
    __shared__ int sb[1024];
    int t = threadIdx.x;
    const int CH = (NN + 1023) / 1024;
    int lo = t * CH;
    int hi = min(lo + CH, NN);
    int s = 0;
    for (int i = lo; i < hi; i++) s += g_cnt[i];
    sb[t] = s;
    __syncthreads();
    for (int off = 1; off < 1024; off <<= 1) {
        int v = (t >= off) ? sb[t - off] : 0;
        __syncthreads();
        sb[t] += v;
        __syncthreads();
    }
    int run = (t > 0) ? sb[t - 1] : 0;
    for (int i = lo; i < hi; i++) {
        g_rowptr[i] = run;
        run += g_cnt[i];
        g_cnt[i] = 0;               // reset for scatter fill
    }
    if (t == 0) g_rowptr[NN] = EL;
}

__global__ void scatter_kernel(const int* __restrict__ src, const int* __restrict__ dst) {
    int e = blockIdx.x * blockDim.x + threadIdx.x;
    if (e >= EL) return;
    int s, d;
    if (e < EE) { s = src[e]; d = dst[e]; }
    else        { s = d = e - EE; }
    int pos = g_rowptr[d] + atomicAdd(&g_cnt[d], 1);
    g_col_src[pos] = s;
    g_col_eid[pos] = e;
    g_perm[e] = pos;
}

// loop_attr: per-node mean of incoming real-edge attrs (warp/node, lane = dim)
__global__ void loop_attr_kernel(const float* __restrict__ ea) {
    int w = (blockIdx.x * blockDim.x + threadIdx.x) >> 5;
    int lane = threadIdx.x & 31;
    if (w >= NN) return;
    int p0 = g_rowptr[w], p1 = g_rowptr[w + 1];
    float s = 0.f;
    int c = 0;
    for (int p = p0; p < p1; p++) {
        int eid = g_col_eid[p];
        if (eid < EE) { s += ea[(size_t)eid * ED + lane]; c++; }
    }
    g_loop[w * ED + lane] = (c > 0) ? s / (float)c : 0.f;
}

// ---------------- GEMM A: 128x128x8 tile, 8x8 micro-tile ----------------------
// Split-column mapping: thread covers cols [tx*4, tx*4+3] and [64+tx*4, 64+tx*4+3]
// -> Bs LDS.128 reads are stride-16B (2-phase, conflict-free) instead of the
//    stride-32B 4-way-conflicted reads of the contiguous tx*8 mapping.
__global__ void gemm128_kernel(const float* __restrict__ x_ext, int use_ext,
                               const float* __restrict__ W, int K, int Nout) {
    __shared__ float As[2][8][132];
    __shared__ float Bs[2][8][128];
    const float* A = use_ext ? x_ext : g_act;
    int t = threadIdx.x;
    int tx = t & 15;
    int ty = t >> 4;
    int row0 = blockIdx.x * 128, col0 = blockIdx.y * 128;

    int ar = t >> 1, ak = (t & 1) * 4;
    int arow = min(row0 + ar, NN - 1);
    const float* Ap = A + (size_t)arow * K + ak;
    int br = t >> 5, bc = (t & 31) * 4;
    const float* Wp = W + (size_t)br * Nout + col0 + bc;

    int ktiles = K >> 3;
    float4 pa = *(const float4*)(Ap);
    float4 pb = *(const float4*)(Wp);

    float acc[8][8];
#pragma unroll
    for (int i = 0; i < 8; i++)
#pragma unroll
        for (int j = 0; j < 8; j++) acc[i][j] = 0.f;

    for (int kt = 0; kt < ktiles; kt++) {
        int cbuf = kt & 1;
        As[cbuf][ak + 0][ar] = pa.x;
        As[cbuf][ak + 1][ar] = pa.y;
        As[cbuf][ak + 2][ar] = pa.z;
        As[cbuf][ak + 3][ar] = pa.w;
        *(float4*)&Bs[cbuf][br][bc] = pb;
        __syncthreads();

        if (kt + 1 < ktiles) {
            int k0 = (kt + 1) << 3;
            pa = *(const float4*)(Ap + k0);
            pb = *(const float4*)(Wp + (size_t)k0 * Nout);
        }

#pragma unroll
        for (int kk = 0; kk < 8; kk++) {
            float4 a0 = *(const float4*)&As[cbuf][kk][ty * 8];
            float4 a1 = *(const float4*)&As[cbuf][kk][ty * 8 + 4];
            float4 b0 = *(const float4*)&Bs[cbuf][kk][tx * 4];        // cols tx*4..+3
            float4 b1 = *(const float4*)&Bs[cbuf][kk][64 + tx * 4];   // cols 64+tx*4..+3
            acc[0][0] += a0.x * b0.x; acc[0][1] += a0.x * b0.y; acc[0][2] += a0.x * b0.z; acc[0][3] += a0.x * b0.w;
            acc[0][4] += a0.x * b1.x; acc[0][5] += a0.x * b1.y; acc[0][6] += a0.x * b1.z; acc[0][7] += a0.x * b1.w;
            acc[1][0] += a0.y * b0.x; acc[1][1] += a0.y * b0.y; acc[1][2] += a0.y * b0.z; acc[1][3] += a0.y * b0.w;
            acc[1][4] += a0.y * b1.x; acc[1][5] += a0.y * b1.y; acc[1][6] += a0.y * b1.z; acc[1][7] += a0.y * b1.w;
            acc[2][0] += a0.z * b0.x; acc[2][1] += a0.z * b0.y; acc[2][2] += a0.z * b0.z; acc[2][3] += a0.z * b0.w;
            acc[2][4] += a0.z * b1.x; acc[2][5] += a0.z * b1.y; acc[2][6] += a0.z * b1.z; acc[2][7] += a0.z * b1.w;
            acc[3][0] += a0.w * b0.x; acc[3][1] += a0.w * b0.y; acc[3][2] += a0.w * b0.z; acc[3][3] += a0.w * b0.w;
            acc[3][4] += a0.w * b1.x; acc[3][5] += a0.w * b1.y; acc[3][6] += a0.w * b1.z; acc[3][7] += a0.w * b1.w;
            acc[4][0] += a1.x * b0.x; acc[4][1] += a1.x * b0.y; acc[4][2] += a1.x * b0.z; acc[4][3] += a1.x * b0.w;
            acc[4][4] += a1.x * b1.x; acc[4][5] += a1.x * b1.y; acc[4][6] += a1.x * b1.z; acc[4][7] += a1.x * b1.w;
            acc[5][0] += a1.y * b0.x; acc[5][1] += a1.y * b0.y; acc[5][2] += a1.y * b0.z; acc[5][3] += a1.y * b0.w;
            acc[5][4] += a1.y * b1.x; acc[5][5] += a1.y * b1.y; acc[5][6] += a1.y * b1.z; acc[5][7] += a1.y * b1.w;
            acc[6][0] += a1.z * b0.x; acc[6][1] += a1.z * b0.y; acc[6][2] += a1.z * b0.z; acc[6][3] += a1.z * b0.w;
            acc[6][4] += a1.z * b1.x; acc[6][5] += a1.z * b1.y; acc[6][6] += a1.z * b1.z; acc[6][7] += a1.z * b1.w;
            acc[7][0] += a1.w * b0.x; acc[7][1] += a1.w * b0.y; acc[7][2] += a1.w * b0.z; acc[7][3] += a1.w * b0.w;
            acc[7][4] += a1.w * b1.x; acc[7][5] += a1.w * b1.y; acc[7][6] += a1.w * b1.z; acc[7][7] += a1.w * b1.w;
        }
        __syncthreads();
    }

    int gcol0 = col0 + tx * 4;
    int gcol1 = col0 + 64 + tx * 4;
#pragma unroll
    for (int i = 0; i < 8; i++) {
        int gr = row0 + ty * 8 + i;
        if (gr < NN) {
            *(float4*)&g_h[(size_t)gr * Nout + gcol0] = make_float4(acc[i][0], acc[i][1], acc[i][2], acc[i][3]);
            *(float4*)&g_h[(size_t)gr * Nout + gcol1] = make_float4(acc[i][4], acc[i][5], acc[i][6], acc[i][7]);
        }
    }
}

// ---------------- GEMM B: 128x64x16 tile, 8x4 micro-tile (Nout = 64) ----------
__global__ void gemm64_kernel(const float* __restrict__ x_ext, int use_ext,
                              const float* __restrict__ W, int K, int Nout) {
    __shared__ float As[2][16][132];
    __shared__ float Bs[2][16][64];
    const float* A = use_ext ? x_ext : g_act;
    int t = threadIdx.x;
    int tx = t & 15;
    int ty = t >> 4;
    int row0 = blockIdx.x * 128, col0 = blockIdx.y * 64;

    int ar0 = t >> 2, ak = (t & 3) * 4;
    int arowA = min(row0 + ar0,      NN - 1);
    int arowB = min(row0 + ar0 + 64, NN - 1);
    const float* ApA = A + (size_t)arowA * K + ak;
    const float* ApB = A + (size_t)arowB * K + ak;
    int br = t >> 4, bc = (t & 15) * 4;
    const float* Wp = W + (size_t)br * Nout + col0 + bc;

    int ktiles = K >> 4;
    float4 pa0 = *(const float4*)(ApA);
    float4 pa1 = *(const float4*)(ApB);
    float4 pb  = *(const float4*)(Wp);

    float acc[8][4];
#pragma unroll
    for (int i = 0; i < 8; i++)
#pragma unroll
        for (int j = 0; j < 4; j++) acc[i][j] = 0.f;

    for (int kt = 0; kt < ktiles; kt++) {
        int cbuf = kt & 1;
        As[cbuf][ak + 0][ar0] = pa0.x;  As[cbuf][ak + 1][ar0] = pa0.y;
        As[cbuf][ak + 2][ar0] = pa0.z;  As[cbuf][ak + 3][ar0] = pa0.w;
        As[cbuf][ak + 0][ar0 + 64] = pa1.x;  As[cbuf][ak + 1][ar0 + 64] = pa1.y;
        As[cbuf][ak + 2][ar0 + 64] = pa1.z;  As[cbuf][ak + 3][ar0 + 64] = pa1.w;
        *(float4*)&Bs[cbuf][br][bc] = pb;
        __syncthreads();

        if (kt + 1 < ktiles) {
            int k0 = (kt + 1) << 4;
            pa0 = *(const float4*)(ApA + k0);
            pa1 = *(const float4*)(ApB + k0);
            pb  = *(const float4*)(Wp + (size_t)k0 * Nout);
        }

#pragma unroll
        for (int kk = 0; kk < 16; kk++) {
            float4 a0 = *(const float4*)&As[cbuf][kk][ty * 8];
            float4 a1 = *(const float4*)&As[cbuf][kk][ty * 8 + 4];
            float4 b  = *(const float4*)&Bs[cbuf][kk][tx * 4];
            acc[0][0] += a0.x * b.x; acc[0][1] += a0.x * b.y; acc[0][2] += a0.x * b.z; acc[0][3] += a0.x * b.w;
            acc[1][0] += a0.y * b.x; acc[1][1] += a0.y * b.y; acc[1][2] += a0.y * b.z; acc[1][3] += a0.y * b.w;
            acc[2][0] += a0.z * b.x; acc[2][1] += a0.z * b.y; acc[2][2] += a0.z * b.z; acc[2][3] += a0.z * b.w;
            acc[3][0] += a0.w * b.x; acc[3][1] += a0.w * b.y; acc[3][2] += a0.w * b.z; acc[3][3] += a0.w * b.w;
            acc[4][0] += a1.x * b.x; acc[4][1] += a1.x * b.y; acc[4][2] += a1.x * b.z; acc[4][3] += a1.x * b.w;
            acc[5][0] += a1.y * b.x; acc[5][1] += a1.y * b.y; acc[5][2] += a1.y * b.z; acc[5][3] += a1.y * b.w;
            acc[6][0] += a1.z * b.x; acc[6][1] += a1.z * b.y; acc[6][2] += a1.z * b.z; acc[6][3] += a1.z * b.w;
            acc[7][0] += a1.w * b.x; acc[7][1] += a1.w * b.y; acc[7][2] += a1.w * b.z; acc[7][3] += a1.w * b.w;
        }
        __syncthreads();
    }

    int gcol = col0 + tx * 4;
#pragma unroll
    for (int i = 0; i < 8; i++) {
        int gr = row0 + ty * 8 + i;
        if (gr < NN)
            *(float4*)&g_h[(size_t)gr * Nout + gcol] =
                make_float4(acc[i][0], acc[i][1], acc[i][2], acc[i][3]);
    }
}

// ---------------- per-node attention scalars ----------------------------------
__global__ void att_node_kernel(const float* __restrict__ att, int heads, int out_c) {
    int gw   = (blockIdx.x * blockDim.x + threadIdx.x) >> 5;
    int lane = threadIdx.x & 31;
    if (gw >= NN * heads) return;
    int n = gw / heads, hh = gw - n * heads;
    int hd = heads * out_c;
    int stride = 2 * out_c + ED;
    const float* hp = g_h + (size_t)n * hd + hh * out_c;
    const float* ai = att + hh * stride;
    const float* aj = ai + out_c;
    float si = 0.f, sj = 0.f;
    for (int j = lane; j < out_c; j += 32) {
        float v = hp[j];
        si += v * ai[j];
        sj += v * aj[j];
    }
#pragma unroll
    for (int o = 16; o > 0; o >>= 1) {
        si += __shfl_xor_sync(0xffffffffu, si, o);
        sj += __shfl_xor_sync(0xffffffffu, sj, o);
    }
    if (lane == 0) { g_ai[gw] = si; g_aj[gw] = sj; }
}

// ---------------- edge_pre: gating MLP -> g_eatt (h-independent!) -------------
__global__ void edge_pre_kernel(const float* __restrict__ eattr,
                                const float* __restrict__ ew1, const float* __restrict__ eb1,
                                const float* __restrict__ ew2, const float* __restrict__ eb2,
                                const float* __restrict__ att,
                                int heads, int out_c, int lay) {
    __shared__ float sEA[32][260];   // [k][edge], transposed, conflict-free
    __shared__ float sW1[32 * 16], sB1[16], sW2[16 * 32], sB2[32], sAE[4 * 32];
    int tid = threadIdx.x;
    int base = blockIdx.x * 256;
    int stride = 2 * out_c + ED;

    for (int i = tid; i < 512; i += 128) { sW1[i] = ew1[i]; sW2[i] = ew2[i]; }
    if (tid < 16) sB1[tid] = eb1[tid];
    if (tid < 32) sB2[tid] = eb2[tid];
    for (int i = tid; i < heads * 32; i += 128) {
        int h = i >> 5, k = i & 31;
        sAE[i] = att[h * stride + 2 * out_c + k];
    }
    for (int i = tid; i < 256 * 8; i += 128) {
        int row = i >> 3, q = i & 7;
        int ge = base + row;
        if (ge < EL) {
            const float4* p = (ge < EE) ? (const float4*)(eattr + (size_t)ge * 32)
                                        : (const float4*)(g_loop + (size_t)(ge - EE) * 32);
            float4 v = p[q];
            int k = q * 4;
            sEA[k + 0][row] = v.x;
            sEA[k + 1][row] = v.y;
            sEA[k + 2][row] = v.z;
            sEA[k + 3][row] = v.w;
        }
    }
    __syncthreads();

    int e0 = base + tid;
    int e1 = base + 128 + tid;
    if (e0 >= EL) return;
    bool has1 = (e1 < EL);

    float hb0[16], hb1[16];
#pragma unroll
    for (int j = 0; j < 16; j++) { hb0[j] = sB1[j]; hb1[j] = sB1[j]; }
#pragma unroll
    for (int k = 0; k < 32; k++) {
        float v0 = sEA[k][tid];
        float v1 = sEA[k][tid + 128];
#pragma unroll
        for (int j = 0; j < 16; j++) {
            float w = sW1[k * 16 + j];
            hb0[j] += v0 * w;
            hb1[j] += v1 * w;
        }
    }
#pragma unroll
    for (int j = 0; j < 16; j++) { hb0[j] = fmaxf(hb0[j], 0.f); hb1[j] = fmaxf(hb1[j], 0.f); }

    float ea0_0 = 0.f, ea0_1 = 0.f, ea0_2 = 0.f, ea0_3 = 0.f;
    float ea1_0 = 0.f, ea1_1 = 0.f, ea1_2 = 0.f, ea1_3 = 0.f;
#pragma unroll
    for (int k = 0; k < 32; k++) {
        float t0 = sB2[k], t1 = sB2[k];
#pragma unroll
        for (int j = 0; j < 16; j++) {
            float w = sW2[j * 32 + k];
            t0 += hb0[j] * w;
            t1 += hb1[j] * w;
        }
        float cw0 = 1.f / (1.f + __expf(-t0));
        float cw1 = 1.f / (1.f + __expf(-t1));
        float w0 = sEA[k][tid] * cw0;
        float w1 = sEA[k][tid + 128] * cw1;
        float ae0 = sAE[k], ae1 = sAE[32 + k], ae2 = sAE[64 + k], ae3 = sAE[96 + k];
        ea0_0 += w0 * ae0; ea0_1 += w0 * ae1; ea0_2 += w0 * ae2; ea0_3 += w0 * ae3;
        ea1_0 += w1 * ae0; ea1_1 += w1 * ae1; ea1_2 += w1 * ae2; ea1_3 += w1 * ae3;
    }

    float* dstp = g_eatt + (size_t)lay * EL * 4;
    *(float4*)(dstp + (size_t)e0 * 4) = make_float4(ea0_0, ea0_1, ea0_2, ea0_3);
    if (has1)
        *(float4*)(dstp + (size_t)e1 * 4) = make_float4(ea1_0, ea1_1, ea1_2, ea1_3);
}

// ---------------- edge_fin: alpha = exp(leaky(ai+aj+eatt)) -> sorted slot -----
__global__ void edge_fin_kernel(const int* __restrict__ src, const int* __restrict__ dst,
                                int heads, int lay) {
    int e = blockIdx.x * blockDim.x + threadIdx.x;
    if (e >= EL) return;
    int s, d;
    if (e < EE) { s = src[e]; d = dst[e]; }
    else        { s = d = e - EE; }
    int pos = g_perm[e];
    const float* ep = g_eatt + (size_t)lay * EL * 4 + (size_t)e * 4;
    if (heads == 4) {
        float4 et  = *(const float4*)ep;
        float4 aid = *(const float4*)(g_ai + d * 4);
        float4 ajs = *(const float4*)(g_aj + s * 4);
        float a0 = aid.x + ajs.x + et.x;
        float a1 = aid.y + ajs.y + et.y;
        float a2 = aid.z + ajs.z + et.z;
        float a3 = aid.w + ajs.w + et.w;
        a0 = fminf((a0 > 0.f) ? a0 : 0.2f * a0, 80.f);
        a1 = fminf((a1 > 0.f) ? a1 : 0.2f * a1, 80.f);
        a2 = fminf((a2 > 0.f) ? a2 : 0.2f * a2, 80.f);
        a3 = fminf((a3 > 0.f) ? a3 : 0.2f * a3, 80.f);
        *(float4*)(g_alpha + (size_t)pos * 4) =
            make_float4(__expf(a0), __expf(a1), __expf(a2), __expf(a3));
    } else {
        float a = g_ai[d] + g_aj[s] + ep[0];
        a = fminf((a > 0.f) ? a : 0.2f * a, 80.f);
        g_alpha[pos] = __expf(a);
    }
}

// ---------------- fused aggregate + softmax norm + bias (+BN+ELU) -------------
__global__ void agg4_kernel(int lw2, int outdim, int heads, int csh,
                            const float* __restrict__ bias,
                            const float* __restrict__ gamma,
                            const float* __restrict__ beta,
                            const float* __restrict__ mean,
                            const float* __restrict__ var) {
    int gw   = (blockIdx.x * blockDim.x + threadIdx.x) >> 5;
    int lane = threadIdx.x & 31;
    int w    = gw >> lw2;
    if (w >= NN) return;
    int wi   = gw & ((1 << lw2) - 1);
    int col0 = wi * 128 + lane * 4;
    int head = col0 >> csh;

    int p0 = g_rowptr[w], p1 = g_rowptr[w + 1];
    float a0 = 0.f, a1 = 0.f, a2 = 0.f, a3 = 0.f, ss = 0.f;
    const float* hb = g_h + col0;
    for (int p = p0; p < p1; p++) {
        int s = g_col_src[p];
        float wg = g_alpha[p * heads + head];
        ss += wg;
        float4 v = *(const float4*)(hb + (size_t)s * outdim);
        a0 += wg * v.x; a1 += wg * v.y; a2 += wg * v.z; a3 += wg * v.w;
    }
    float r = 1.f / (ss + 1e-16f);
    float v0 = a0 * r + bias[col0 + 0];
    float v1 = a1 * r + bias[col0 + 1];
    float v2 = a2 * r + bias[col0 + 2];
    float v3 = a3 * r + bias[col0 + 3];
    v0 = (v0 - mean[col0 + 0]) * rsqrtf(var[col0 + 0] + 1e-5f) * gamma[col0 + 0] + beta[col0 + 0];
    v1 = (v1 - mean[col0 + 1]) * rsqrtf(var[col0 + 1] + 1e-5f) * gamma[col0 + 1] + beta[col0 + 1];
    v2 = (v2 - mean[col0 + 2]) * rsqrtf(var[col0 + 2] + 1e-5f) * gamma[col0 + 2] + beta[col0 + 2];
    v3 = (v3 - mean[col0 + 3]) * rsqrtf(var[col0 + 3] + 1e-5f) * gamma[col0 + 3] + beta[col0 + 3];
    v0 = (v0 > 0.f) ? v0 : expm1f(v0);
    v1 = (v1 > 0.f) ? v1 : expm1f(v1);
    v2 = (v2 > 0.f) ? v2 : expm1f(v2);
    v3 = (v3 > 0.f) ? v3 : expm1f(v3);
    float4 out = make_float4(v0, v1, v2, v3);
    *(float4*)(g_act + (size_t)w * outdim + col0) = out;
}

// last layer: outdim=64, heads=1, 2 cols/lane, bias only, write d_out
__global__ void agg2_kernel(const float* __restrict__ bias, float* __restrict__ outp) {
    int gw   = (blockIdx.x * blockDim.x + threadIdx.x) >> 5;
    int lane = threadIdx.x & 31;
    if (gw >= NN) return;
    int col0 = lane * 2;

    int p0 = g_rowptr[gw], p1 = g_rowptr[gw + 1];
    float a0 = 0.f, a1 = 0.f, ss = 0.f;
    const float* hb = g_h + col0;
    for (int p = p0; p < p1; p++) {
        int s = g_col_src[p];
        float wg = g_alpha[p];
        ss += wg;
        float2 v = *(const float2*)(hb + (size_t)s * 64);
        a0 += wg * v.x; a1 += wg * v.y;
    }
    float r = 1.f / (ss + 1e-16f);
    float2 out = make_float2(a0 * r + bias[col0], a1 * r + bias[col0 + 1]);
    *(float2*)(outp + (size_t)gw * 64 + col0) = out;
}

// ---------------- host (R10 schedule, verbatim) --------------------------------
extern "C" void kernel_launch(void* const* d_in, const int* in_sizes, int n_in,
                              void* d_out, int out_size) {
    const float* x     = (const float*)d_in[0];
    const int*   src   = (const int*)d_in[1];
    const int*   dst   = src + EE;
    const float* eattr = (const float*)d_in[2];

    struct LP {
        const float *W, *ew1, *eb1, *ew2, *eb2, *att, *bias;
        int K, out_c, heads;
        const float *gamma, *beta, *mean, *var;
    };
    LP lp[3];
    lp[0] = { (const float*)d_in[3],  (const float*)d_in[4],  (const float*)d_in[5],
              (const float*)d_in[6],  (const float*)d_in[7],  (const float*)d_in[8],
              (const float*)d_in[9],  128, 64, 4,
              (const float*)d_in[24], (const float*)d_in[25], (const float*)d_in[26], (const float*)d_in[27] };
    lp[1] = { (const float*)d_in[10], (const float*)d_in[11], (const float*)d_in[12],
              (const float*)d_in[13], (const float*)d_in[14], (const float*)d_in[15],
              (const float*)d_in[16], 256, 32, 4,
              (const float*)d_in[28], (const float*)d_in[29], (const float*)d_in[30], (const float*)d_in[31] };
    lp[2] = { (const float*)d_in[17], (const float*)d_in[18], (const float*)d_in[19],
              (const float*)d_in[20], (const float*)d_in[21], (const float*)d_in[22],
              (const float*)d_in[23], 128, 64, 1,
              nullptr, nullptr, nullptr, nullptr };

    // one-time stream/event setup (created outside capture, reused)
    static cudaStream_t s2 = nullptr;
    static cudaEvent_t evFork = nullptr, evE[3] = {nullptr, nullptr, nullptr};
    if (!s2) {
        cudaStreamCreateWithFlags(&s2, cudaStreamNonBlocking);
        cudaEventCreateWithFlags(&evFork, cudaEventDisableTiming);
        for (int i = 0; i < 3; i++) cudaEventCreateWithFlags(&evE[i], cudaEventDisableTiming);
    }

    // ---- fork side stream: CSR + loop_attr + all three edge_pre passes ----
    cudaEventRecord(evFork, 0);
    cudaStreamWaitEvent(s2, evFork, 0);

    initcnt_kernel<<<(NN + 255) / 256, 256, 0, s2>>>();                 // ord 0
    hist_kernel<<<(EE + 255) / 256, 256, 0, s2>>>(dst);                 // ord 1
    scan_kernel<<<1, 1024, 0, s2>>>();                                  // ord 2

    {   // gemm L0 at ordinal 3 (profiled slot)
        dim3 ggrid((NN + 127) / 128, 2);
        gemm128_kernel<<<ggrid, 256>>>(x, 1, lp[0].W, 128, 256);        // ord 3
    }

    scatter_kernel<<<(EL + 255) / 256, 256, 0, s2>>>(src, dst);         // ord 4
    loop_attr_kernel<<<(NN * 32 + 255) / 256, 256, 0, s2>>>(eattr);     // ord 5

    for (int L = 0; L < 3; L++) {
        const LP& p = lp[L];
        edge_pre_kernel<<<(EL + 255) / 256, 128, 0, s2>>>(eattr,
            p.ew1, p.eb1, p.ew2, p.eb2, p.att, p.heads, p.out_c, L);
        cudaEventRecord(evE[L], s2);
    }

    att_node_kernel<<<(NN * 4 * 32 + 255) / 256, 256>>>(lp[0].att, 4, 64);

    for (int L = 0; L < 3; L++) {
        const LP& p = lp[L];
        int outdim = p.heads * p.out_c;                     // 256, 128, 64

        if (L > 0) {
            if (outdim >= 128) {
                dim3 ggrid((NN + 127) / 128, outdim / 128);
                gemm128_kernel<<<ggrid, 256>>>(x, 0, p.W, p.K, outdim);
            } else {
                dim3 ggrid((NN + 127) / 128, outdim / 64);
                gemm64_kernel<<<ggrid, 256>>>(x, 0, p.W, p.K, outdim);
            }
            att_node_kernel<<<(NN * p.heads * 32 + 255) / 256, 256>>>(p.att, p.heads, p.out_c);
        }

        cudaStreamWaitEvent(0, evE[L], 0);   // need this layer's edge_pre only
        edge_fin_kernel<<<(EL + 255) / 256, 256>>>(src, dst, p.heads, L);

        if (L == 0) {
            int nwarp = NN * 2;          // WPN=2
            agg4_kernel<<<(nwarp + 7) / 8, 256>>>(1, 256, 4, 6,
                                                  p.bias, p.gamma, p.beta, p.mean, p.var);
        } else if (L == 1) {
            int nwarp = NN;              // WPN=1
            agg4_kernel<<<(nwarp + 7) / 8, 256>>>(0, 128, 4, 5,
                                                  p.bias, p.gamma, p.beta, p.mean, p.var);
        } else {
            agg2_kernel<<<(NN + 7) / 8, 256>>>(p.bias, (float*)d_out);
        }
    }
}

// round 15
// speedup vs baseline: 1.1421x; 1.0566x over previous
#include <cuda_runtime.h>
#include <math.h>

#define NN 50000
#define EE 400000
#define EL 450000   // E + N self loops
#define ED 32

// ---------------- scratch (static device globals; no allocation) -------------
__device__ float g_h[NN * 256];      // projected features
__device__ float g_act[NN * 256];    // activated layer input (layers 2,3)
__device__ float g_loop[NN * ED];    // loop_attr (segment mean of edge_attr)
__device__ float g_ai[NN * 4];
__device__ float g_aj[NN * 4];
__device__ float g_alpha[EL * 4];    // exp weights, sorted by dst
__device__ float g_eatt[3 * EL * 4]; // per-layer edge-MLP attention term (by edge id)
__device__ int   g_rowptr[NN + 1];
__device__ int   g_cnt[NN];
__device__ int   g_col_src[EL];      // src node per sorted edge
__device__ int   g_col_eid[EL];      // original edge id per sorted edge
__device__ int   g_perm[EL];         // original edge -> sorted position

// ---------------- CSR build (scalar-only kernels) -----------------------------
__global__ void initcnt_kernel() {
    int i = blockIdx.x * blockDim.x + threadIdx.x;
    if (i < NN) g_cnt[i] = 1;        // self loop
}

__global__ void hist_kernel(const int* __restrict__ dst) {
    int e = blockIdx.x * blockDim.x + threadIdx.x;
    if (e < EE) atomicAdd(&g_cnt[dst[e]], 1);
}

__global__ void scan_kernel() {
    __shared__ int sb[1024];
    int t = threadIdx.x;
    const int CH = (NN + 1023) / 1024;
    int lo = t * CH;
    int hi = min(lo + CH, NN);
    int s = 0;
    for (int i = lo; i < hi; i++) s += g_cnt[i];
    sb[t] = s;
    __syncthreads();
    for (int off = 1; off < 1024; off <<= 1) {
        int v = (t >= off) ? sb[t - off] : 0;
        __syncthreads();
        sb[t] += v;
        __syncthreads();
    }
    int run = (t > 0) ? sb[t - 1] : 0;
    for (int i = lo; i < hi; i++) {
        g_rowptr[i] = run;
        run += g_cnt[i];
        g_cnt[i] = 0;               // reset for scatter fill
    }
    if (t == 0) g_rowptr[NN] = EL;
}

__global__ void scatter_kernel(const int* __restrict__ src, const int* __restrict__ dst) {
    int e = blockIdx.x * blockDim.x + threadIdx.x;
    if (e >= EL) return;
    int s, d;
    if (e < EE) { s = src[e]; d = dst[e]; }
    else        { s = d = e - EE; }
    int pos = g_rowptr[d] + atomicAdd(&g_cnt[d], 1);
    g_col_src[pos] = s;
    g_col_eid[pos] = e;
    g_perm[e] = pos;
}

// loop_attr: per-node mean of incoming real-edge attrs (warp/node, lane = dim)
__global__ void loop_attr_kernel(const float* __restrict__ ea) {
    int w = (blockIdx.x * blockDim.x + threadIdx.x) >> 5;
    int lane = threadIdx.x & 31;
    if (w >= NN) return;
    int p0 = g_rowptr[w], p1 = g_rowptr[w + 1];
    float s = 0.f;
    int c = 0;
    for (int p = p0; p < p1; p++) {
        int eid = g_col_eid[p];
        if (eid < EE) { s += ea[(size_t)eid * ED + lane]; c++; }
    }
    g_loop[w * ED + lane] = (c > 0) ? s / (float)c : 0.f;
}

// ---------------- GEMM A: 128x128x8 tile, 8x8 micro-tile (split-column) -------
__global__ void gemm128_kernel(const float* __restrict__ x_ext, int use_ext,
                               const float* __restrict__ W, int K, int Nout) {
    __shared__ float As[2][8][132];
    __shared__ float Bs[2][8][128];
    const float* A = use_ext ? x_ext : g_act;
    int t = threadIdx.x;
    int tx = t & 15;
    int ty = t >> 4;
    int row0 = blockIdx.x * 128, col0 = blockIdx.y * 128;

    int ar = t >> 1, ak = (t & 1) * 4;
    int arow = min(row0 + ar, NN - 1);
    const float* Ap = A + (size_t)arow * K + ak;
    int br = t >> 5, bc = (t & 31) * 4;
    const float* Wp = W + (size_t)br * Nout + col0 + bc;

    int ktiles = K >> 3;
    float4 pa = *(const float4*)(Ap);
    float4 pb = *(const float4*)(Wp);

    float acc[8][8];
#pragma unroll
    for (int i = 0; i < 8; i++)
#pragma unroll
        for (int j = 0; j < 8; j++) acc[i][j] = 0.f;

    for (int kt = 0; kt < ktiles; kt++) {
        int cbuf = kt & 1;
        As[cbuf][ak + 0][ar] = pa.x;
        As[cbuf][ak + 1][ar] = pa.y;
        As[cbuf][ak + 2][ar] = pa.z;
        As[cbuf][ak + 3][ar] = pa.w;
        *(float4*)&Bs[cbuf][br][bc] = pb;
        __syncthreads();

        if (kt + 1 < ktiles) {
            int k0 = (kt + 1) << 3;
            pa = *(const float4*)(Ap + k0);
            pb = *(const float4*)(Wp + (size_t)k0 * Nout);
        }

#pragma unroll
        for (int kk = 0; kk < 8; kk++) {
            float4 a0 = *(const float4*)&As[cbuf][kk][ty * 8];
            float4 a1 = *(const float4*)&As[cbuf][kk][ty * 8 + 4];
            float4 b0 = *(const float4*)&Bs[cbuf][kk][tx * 4];        // cols tx*4..+3
            float4 b1 = *(const float4*)&Bs[cbuf][kk][64 + tx * 4];   // cols 64+tx*4..+3
            acc[0][0] += a0.x * b0.x; acc[0][1] += a0.x * b0.y; acc[0][2] += a0.x * b0.z; acc[0][3] += a0.x * b0.w;
            acc[0][4] += a0.x * b1.x; acc[0][5] += a0.x * b1.y; acc[0][6] += a0.x * b1.z; acc[0][7] += a0.x * b1.w;
            acc[1][0] += a0.y * b0.x; acc[1][1] += a0.y * b0.y; acc[1][2] += a0.y * b0.z; acc[1][3] += a0.y * b0.w;
            acc[1][4] += a0.y * b1.x; acc[1][5] += a0.y * b1.y; acc[1][6] += a0.y * b1.z; acc[1][7] += a0.y * b1.w;
            acc[2][0] += a0.z * b0.x; acc[2][1] += a0.z * b0.y; acc[2][2] += a0.z * b0.z; acc[2][3] += a0.z * b0.w;
            acc[2][4] += a0.z * b1.x; acc[2][5] += a0.z * b1.y; acc[2][6] += a0.z * b1.z; acc[2][7] += a0.z * b1.w;
            acc[3][0] += a0.w * b0.x; acc[3][1] += a0.w * b0.y; acc[3][2] += a0.w * b0.z; acc[3][3] += a0.w * b0.w;
            acc[3][4] += a0.w * b1.x; acc[3][5] += a0.w * b1.y; acc[3][6] += a0.w * b1.z; acc[3][7] += a0.w * b1.w;
            acc[4][0] += a1.x * b0.x; acc[4][1] += a1.x * b0.y; acc[4][2] += a1.x * b0.z; acc[4][3] += a1.x * b0.w;
            acc[4][4] += a1.x * b1.x; acc[4][5] += a1.x * b1.y; acc[4][6] += a1.x * b1.z; acc[4][7] += a1.x * b1.w;
            acc[5][0] += a1.y * b0.x; acc[5][1] += a1.y * b0.y; acc[5][2] += a1.y * b0.z; acc[5][3] += a1.y * b0.w;
            acc[5][4] += a1.y * b1.x; acc[5][5] += a1.y * b1.y; acc[5][6] += a1.y * b1.z; acc[5][7] += a1.y * b1.w;
            acc[6][0] += a1.z * b0.x; acc[6][1] += a1.z * b0.y; acc[6][2] += a1.z * b0.z; acc[6][3] += a1.z * b0.w;
            acc[6][4] += a1.z * b1.x; acc[6][5] += a1.z * b1.y; acc[6][6] += a1.z * b1.z; acc[6][7] += a1.z * b1.w;
            acc[7][0] += a1.w * b0.x; acc[7][1] += a1.w * b0.y; acc[7][2] += a1.w * b0.z; acc[7][3] += a1.w * b0.w;
            acc[7][4] += a1.w * b1.x; acc[7][5] += a1.w * b1.y; acc[7][6] += a1.w * b1.z; acc[7][7] += a1.w * b1.w;
        }
        __syncthreads();
    }

    int gcol0 = col0 + tx * 4;
    int gcol1 = col0 + 64 + tx * 4;
#pragma unroll
    for (int i = 0; i < 8; i++) {
        int gr = row0 + ty * 8 + i;
        if (gr < NN) {
            *(float4*)&g_h[(size_t)gr * Nout + gcol0] = make_float4(acc[i][0], acc[i][1], acc[i][2], acc[i][3]);
            *(float4*)&g_h[(size_t)gr * Nout + gcol1] = make_float4(acc[i][4], acc[i][5], acc[i][6], acc[i][7]);
        }
    }
}

// ---------------- GEMM B: 128x64x16 tile, 8x4 micro-tile (Nout = 64) ----------
__global__ void gemm64_kernel(const float* __restrict__ x_ext, int use_ext,
                              const float* __restrict__ W, int K, int Nout) {
    __shared__ float As[2][16][132];
    __shared__ float Bs[2][16][64];
    const float* A = use_ext ? x_ext : g_act;
    int t = threadIdx.x;
    int tx = t & 15;
    int ty = t >> 4;
    int row0 = blockIdx.x * 128, col0 = blockIdx.y * 64;

    int ar0 = t >> 2, ak = (t & 3) * 4;
    int arowA = min(row0 + ar0,      NN - 1);
    int arowB = min(row0 + ar0 + 64, NN - 1);
    const float* ApA = A + (size_t)arowA * K + ak;
    const float* ApB = A + (size_t)arowB * K + ak;
    int br = t >> 4, bc = (t & 15) * 4;
    const float* Wp = W + (size_t)br * Nout + col0 + bc;

    int ktiles = K >> 4;
    float4 pa0 = *(const float4*)(ApA);
    float4 pa1 = *(const float4*)(ApB);
    float4 pb  = *(const float4*)(Wp);

    float acc[8][4];
#pragma unroll
    for (int i = 0; i < 8; i++)
#pragma unroll
        for (int j = 0; j < 4; j++) acc[i][j] = 0.f;

    for (int kt = 0; kt < ktiles; kt++) {
        int cbuf = kt & 1;
        As[cbuf][ak + 0][ar0] = pa0.x;  As[cbuf][ak + 1][ar0] = pa0.y;
        As[cbuf][ak + 2][ar0] = pa0.z;  As[cbuf][ak + 3][ar0] = pa0.w;
        As[cbuf][ak + 0][ar0 + 64] = pa1.x;  As[cbuf][ak + 1][ar0 + 64] = pa1.y;
        As[cbuf][ak + 2][ar0 + 64] = pa1.z;  As[cbuf][ak + 3][ar0 + 64] = pa1.w;
        *(float4*)&Bs[cbuf][br][bc] = pb;
        __syncthreads();

        if (kt + 1 < ktiles) {
            int k0 = (kt + 1) << 4;
            pa0 = *(const float4*)(ApA + k0);
            pa1 = *(const float4*)(ApB + k0);
            pb  = *(const float4*)(Wp + (size_t)k0 * Nout);
        }

#pragma unroll
        for (int kk = 0; kk < 16; kk++) {
            float4 a0 = *(const float4*)&As[cbuf][kk][ty * 8];
            float4 a1 = *(const float4*)&As[cbuf][kk][ty * 8 + 4];
            float4 b  = *(const float4*)&Bs[cbuf][kk][tx * 4];
            acc[0][0] += a0.x * b.x; acc[0][1] += a0.x * b.y; acc[0][2] += a0.x * b.z; acc[0][3] += a0.x * b.w;
            acc[1][0] += a0.y * b.x; acc[1][1] += a0.y * b.y; acc[1][2] += a0.y * b.z; acc[1][3] += a0.y * b.w;
            acc[2][0] += a0.z * b.x; acc[2][1] += a0.z * b.y; acc[2][2] += a0.z * b.z; acc[2][3] += a0.z * b.w;
            acc[3][0] += a0.w * b.x; acc[3][1] += a0.w * b.y; acc[3][2] += a0.w * b.z; acc[3][3] += a0.w * b.w;
            acc[4][0] += a1.x * b.x; acc[4][1] += a1.x * b.y; acc[4][2] += a1.x * b.z; acc[4][3] += a1.x * b.w;
            acc[5][0] += a1.y * b.x; acc[5][1] += a1.y * b.y; acc[5][2] += a1.y * b.z; acc[5][3] += a1.y * b.w;
            acc[6][0] += a1.z * b.x; acc[6][1] += a1.z * b.y; acc[6][2] += a1.z * b.z; acc[6][3] += a1.z * b.w;
            acc[7][0] += a1.w * b.x; acc[7][1] += a1.w * b.y; acc[7][2] += a1.w * b.z; acc[7][3] += a1.w * b.w;
        }
        __syncthreads();
    }

    int gcol = col0 + tx * 4;
#pragma unroll
    for (int i = 0; i < 8; i++) {
        int gr = row0 + ty * 8 + i;
        if (gr < NN)
            *(float4*)&g_h[(size_t)gr * Nout + gcol] =
                make_float4(acc[i][0], acc[i][1], acc[i][2], acc[i][3]);
    }
}

// ---------------- per-node attention scalars ----------------------------------
__global__ void att_node_kernel(const float* __restrict__ att, int heads, int out_c) {
    int gw   = (blockIdx.x * blockDim.x + threadIdx.x) >> 5;
    int lane = threadIdx.x & 31;
    if (gw >= NN * heads) return;
    int n = gw / heads, hh = gw - n * heads;
    int hd = heads * out_c;
    int stride = 2 * out_c + ED;
    const float* hp = g_h + (size_t)n * hd + hh * out_c;
    const float* ai = att + hh * stride;
    const float* aj = ai + out_c;
    float si = 0.f, sj = 0.f;
    for (int j = lane; j < out_c; j += 32) {
        float v = hp[j];
        si += v * ai[j];
        sj += v * aj[j];
    }
#pragma unroll
    for (int o = 16; o > 0; o >>= 1) {
        si += __shfl_xor_sync(0xffffffffu, si, o);
        sj += __shfl_xor_sync(0xffffffffu, sj, o);
    }
    if (lane == 0) { g_ai[gw] = si; g_aj[gw] = sj; }
}

// ---------------- edge_pre: gating MLP -> g_eatt, over edge range -------------
// Real edges [0, EE) need only eattr; self loops [EE, EL) need g_loop.
__global__ void edge_pre_kernel(const float* __restrict__ eattr,
                                const float* __restrict__ ew1, const float* __restrict__ eb1,
                                const float* __restrict__ ew2, const float* __restrict__ eb2,
                                const float* __restrict__ att,
                                int heads, int out_c, int lay,
                                int e_begin, int e_count) {
    __shared__ float sEA[32][260];   // [k][edge], transposed, conflict-free
    __shared__ float sW1[32 * 16], sB1[16], sW2[16 * 32], sB2[32], sAE[4 * 32];
    int tid = threadIdx.x;
    int base = e_begin + blockIdx.x * 256;
    int e_end = e_begin + e_count;
    int stride = 2 * out_c + ED;

    for (int i = tid; i < 512; i += 128) { sW1[i] = ew1[i]; sW2[i] = ew2[i]; }
    if (tid < 16) sB1[tid] = eb1[tid];
    if (tid < 32) sB2[tid] = eb2[tid];
    for (int i = tid; i < heads * 32; i += 128) {
        int h = i >> 5, k = i & 31;
        sAE[i] = att[h * stride + 2 * out_c + k];
    }
    for (int i = tid; i < 256 * 8; i += 128) {
        int row = i >> 3, q = i & 7;
        int ge = base + row;
        if (ge < e_end) {
            const float4* p = (ge < EE) ? (const float4*)(eattr + (size_t)ge * 32)
                                        : (const float4*)(g_loop + (size_t)(ge - EE) * 32);
            float4 v = p[q];
            int k = q * 4;
            sEA[k + 0][row] = v.x;
            sEA[k + 1][row] = v.y;
            sEA[k + 2][row] = v.z;
            sEA[k + 3][row] = v.w;
        }
    }
    __syncthreads();

    int e0 = base + tid;
    int e1 = base + 128 + tid;
    if (e0 >= e_end) return;
    bool has1 = (e1 < e_end);

    float hb0[16], hb1[16];
#pragma unroll
    for (int j = 0; j < 16; j++) { hb0[j] = sB1[j]; hb1[j] = sB1[j]; }
#pragma unroll
    for (int k = 0; k < 32; k++) {
        float v0 = sEA[k][tid];
        float v1 = sEA[k][tid + 128];
#pragma unroll
        for (int j = 0; j < 16; j++) {
            float w = sW1[k * 16 + j];
            hb0[j] += v0 * w;
            hb1[j] += v1 * w;
        }
    }
#pragma unroll
    for (int j = 0; j < 16; j++) { hb0[j] = fmaxf(hb0[j], 0.f); hb1[j] = fmaxf(hb1[j], 0.f); }

    float ea0_0 = 0.f, ea0_1 = 0.f, ea0_2 = 0.f, ea0_3 = 0.f;
    float ea1_0 = 0.f, ea1_1 = 0.f, ea1_2 = 0.f, ea1_3 = 0.f;
#pragma unroll
    for (int k = 0; k < 32; k++) {
        float t0 = sB2[k], t1 = sB2[k];
#pragma unroll
        for (int j = 0; j < 16; j++) {
            float w = sW2[j * 32 + k];
            t0 += hb0[j] * w;
            t1 += hb1[j] * w;
        }
        float cw0 = 1.f / (1.f + __expf(-t0));
        float cw1 = 1.f / (1.f + __expf(-t1));
        float w0 = sEA[k][tid] * cw0;
        float w1 = sEA[k][tid + 128] * cw1;
        float ae0 = sAE[k], ae1 = sAE[32 + k], ae2 = sAE[64 + k], ae3 = sAE[96 + k];
        ea0_0 += w0 * ae0; ea0_1 += w0 * ae1; ea0_2 += w0 * ae2; ea0_3 += w0 * ae3;
        ea1_0 += w1 * ae0; ea1_1 += w1 * ae1; ea1_2 += w1 * ae2; ea1_3 += w1 * ae3;
    }

    float* dstp = g_eatt + (size_t)lay * EL * 4;
    *(float4*)(dstp + (size_t)e0 * 4) = make_float4(ea0_0, ea0_1, ea0_2, ea0_3);
    if (has1)
        *(float4*)(dstp + (size_t)e1 * 4) = make_float4(ea1_0, ea1_1, ea1_2, ea1_3);
}

// ---------------- edge_fin: alpha = exp(leaky(ai+aj+eatt)) -> sorted slot -----
__global__ void edge_fin_kernel(const int* __restrict__ src, const int* __restrict__ dst,
                                int heads, int lay) {
    int e = blockIdx.x * blockDim.x + threadIdx.x;
    if (e >= EL) return;
    int s, d;
    if (e < EE) { s = src[e]; d = dst[e]; }
    else        { s = d = e - EE; }
    int pos = g_perm[e];
    const float* ep = g_eatt + (size_t)lay * EL * 4 + (size_t)e * 4;
    if (heads == 4) {
        float4 et  = *(const float4*)ep;
        float4 aid = *(const float4*)(g_ai + d * 4);
        float4 ajs = *(const float4*)(g_aj + s * 4);
        float a0 = aid.x + ajs.x + et.x;
        float a1 = aid.y + ajs.y + et.y;
        float a2 = aid.z + ajs.z + et.z;
        float a3 = aid.w + ajs.w + et.w;
        a0 = fminf((a0 > 0.f) ? a0 : 0.2f * a0, 80.f);
        a1 = fminf((a1 > 0.f) ? a1 : 0.2f * a1, 80.f);
        a2 = fminf((a2 > 0.f) ? a2 : 0.2f * a2, 80.f);
        a3 = fminf((a3 > 0.f) ? a3 : 0.2f * a3, 80.f);
        *(float4*)(g_alpha + (size_t)pos * 4) =
            make_float4(__expf(a0), __expf(a1), __expf(a2), __expf(a3));
    } else {
        float a = g_ai[d] + g_aj[s] + ep[0];
        a = fminf((a > 0.f) ? a : 0.2f * a, 80.f);
        g_alpha[pos] = __expf(a);
    }
}

// ---------------- fused aggregate + softmax norm + bias (+BN+ELU) -------------
__global__ void agg4_kernel(int lw2, int outdim, int heads, int csh,
                            const float* __restrict__ bias,
                            const float* __restrict__ gamma,
                            const float* __restrict__ beta,
                            const float* __restrict__ mean,
                            const float* __restrict__ var) {
    int gw   = (blockIdx.x * blockDim.x + threadIdx.x) >> 5;
    int lane = threadIdx.x & 31;
    int w    = gw >> lw2;
    if (w >= NN) return;
    int wi   = gw & ((1 << lw2) - 1);
    int col0 = wi * 128 + lane * 4;
    int head = col0 >> csh;

    int p0 = g_rowptr[w], p1 = g_rowptr[w + 1];
    float a0 = 0.f, a1 = 0.f, a2 = 0.f, a3 = 0.f, ss = 0.f;
    const float* hb = g_h + col0;
    for (int p = p0; p < p1; p++) {
        int s = g_col_src[p];
        float wg = g_alpha[p * heads + head];
        ss += wg;
        float4 v = *(const float4*)(hb + (size_t)s * outdim);
        a0 += wg * v.x; a1 += wg * v.y; a2 += wg * v.z; a3 += wg * v.w;
    }
    float r = 1.f / (ss + 1e-16f);
    float v0 = a0 * r + bias[col0 + 0];
    float v1 = a1 * r + bias[col0 + 1];
    float v2 = a2 * r + bias[col0 + 2];
    float v3 = a3 * r + bias[col0 + 3];
    v0 = (v0 - mean[col0 + 0]) * rsqrtf(var[col0 + 0] + 1e-5f) * gamma[col0 + 0] + beta[col0 + 0];
    v1 = (v1 - mean[col0 + 1]) * rsqrtf(var[col0 + 1] + 1e-5f) * gamma[col0 + 1] + beta[col0 + 1];
    v2 = (v2 - mean[col0 + 2]) * rsqrtf(var[col0 + 2] + 1e-5f) * gamma[col0 + 2] + beta[col0 + 2];
    v3 = (v3 - mean[col0 + 3]) * rsqrtf(var[col0 + 3] + 1e-5f) * gamma[col0 + 3] + beta[col0 + 3];
    v0 = (v0 > 0.f) ? v0 : expm1f(v0);
    v1 = (v1 > 0.f) ? v1 : expm1f(v1);
    v2 = (v2 > 0.f) ? v2 : expm1f(v2);
    v3 = (v3 > 0.f) ? v3 : expm1f(v3);
    float4 out = make_float4(v0, v1, v2, v3);
    *(float4*)(g_act + (size_t)w * outdim + col0) = out;
}

// last layer: outdim=64, heads=1, 2 cols/lane, bias only, write d_out
__global__ void agg2_kernel(const float* __restrict__ bias, float* __restrict__ outp) {
    int gw   = (blockIdx.x * blockDim.x + threadIdx.x) >> 5;
    int lane = threadIdx.x & 31;
    if (gw >= NN) return;
    int col0 = lane * 2;

    int p0 = g_rowptr[gw], p1 = g_rowptr[gw + 1];
    float a0 = 0.f, a1 = 0.f, ss = 0.f;
    const float* hb = g_h + col0;
    for (int p = p0; p < p1; p++) {
        int s = g_col_src[p];
        float wg = g_alpha[p];
        ss += wg;
        float2 v = *(const float2*)(hb + (size_t)s * 64);
        a0 += wg * v.x; a1 += wg * v.y;
    }
    float r = 1.f / (ss + 1e-16f);
    float2 out = make_float2(a0 * r + bias[col0], a1 * r + bias[col0 + 1]);
    *(float2*)(outp + (size_t)gw * 64 + col0) = out;
}

// ---------------- host ---------------------------------------------------------
extern "C" void kernel_launch(void* const* d_in, const int* in_sizes, int n_in,
                              void* d_out, int out_size) {
    const float* x     = (const float*)d_in[0];
    const int*   src   = (const int*)d_in[1];
    const int*   dst   = src + EE;
    const float* eattr = (const float*)d_in[2];

    struct LP {
        const float *W, *ew1, *eb1, *ew2, *eb2, *att, *bias;
        int K, out_c, heads;
        const float *gamma, *beta, *mean, *var;
    };
    LP lp[3];
    lp[0] = { (const float*)d_in[3],  (const float*)d_in[4],  (const float*)d_in[5],
              (const float*)d_in[6],  (const float*)d_in[7],  (const float*)d_in[8],
              (const float*)d_in[9],  128, 64, 4,
              (const float*)d_in[24], (const float*)d_in[25], (const float*)d_in[26], (const float*)d_in[27] };
    lp[1] = { (const float*)d_in[10], (const float*)d_in[11], (const float*)d_in[12],
              (const float*)d_in[13], (const float*)d_in[14], (const float*)d_in[15],
              (const float*)d_in[16], 256, 32, 4,
              (const float*)d_in[28], (const float*)d_in[29], (const float*)d_in[30], (const float*)d_in[31] };
    lp[2] = { (const float*)d_in[17], (const float*)d_in[18], (const float*)d_in[19],
              (const float*)d_in[20], (const float*)d_in[21], (const float*)d_in[22],
              (const float*)d_in[23], 128, 64, 1,
              nullptr, nullptr, nullptr, nullptr };

    // one-time stream/event setup (created outside capture, reused)
    static cudaStream_t s2 = nullptr, s3 = nullptr;
    static cudaEvent_t evFork = nullptr;
    static cudaEvent_t evSelf[3] = {nullptr, nullptr, nullptr};   // s2: CSR+loop+self-pre L
    static cudaEvent_t evReal[3] = {nullptr, nullptr, nullptr};   // s3: real-pre L
    if (!s2) {
        cudaStreamCreateWithFlags(&s2, cudaStreamNonBlocking);
        cudaStreamCreateWithFlags(&s3, cudaStreamNonBlocking);
        cudaEventCreateWithFlags(&evFork, cudaEventDisableTiming);
        for (int i = 0; i < 3; i++) {
            cudaEventCreateWithFlags(&evSelf[i], cudaEventDisableTiming);
            cudaEventCreateWithFlags(&evReal[i], cudaEventDisableTiming);
        }
    }

    // ---- fork: s3 = real-edge pre (no deps); s2 = CSR + loop_attr + self-pre --
    cudaEventRecord(evFork, 0);
    cudaStreamWaitEvent(s2, evFork, 0);
    cudaStreamWaitEvent(s3, evFork, 0);

    initcnt_kernel<<<(NN + 255) / 256, 256, 0, s2>>>();                 // ord 0
    hist_kernel<<<(EE + 255) / 256, 256, 0, s2>>>(dst);                 // ord 1
    scan_kernel<<<1, 1024, 0, s2>>>();                                  // ord 2

    {   // gemm L0 at ordinal 3 (profiled slot)
        dim3 ggrid((NN + 127) / 128, 2);
        gemm128_kernel<<<ggrid, 256>>>(x, 1, lp[0].W, 128, 256);        // ord 3
    }

    // s3: real-edge gating MLP for all 3 layers (only needs eattr + weights)
    for (int L = 0; L < 3; L++) {
        const LP& p = lp[L];
        edge_pre_kernel<<<(EE + 255) / 256, 128, 0, s3>>>(eattr,
            p.ew1, p.eb1, p.ew2, p.eb2, p.att, p.heads, p.out_c, L, 0, EE);
        cudaEventRecord(evReal[L], s3);
    }

    scatter_kernel<<<(EL + 255) / 256, 256, 0, s2>>>(src, dst);
    loop_attr_kernel<<<(NN * 32 + 255) / 256, 256, 0, s2>>>(eattr);

    // s2: self-loop gating MLP per layer (needs g_loop)
    for (int L = 0; L < 3; L++) {
        const LP& p = lp[L];
        edge_pre_kernel<<<(NN + 255) / 256, 128, 0, s2>>>(eattr,
            p.ew1, p.eb1, p.ew2, p.eb2, p.att, p.heads, p.out_c, L, EE, NN);
        cudaEventRecord(evSelf[L], s2);
    }

    att_node_kernel<<<(NN * 4 * 32 + 255) / 256, 256>>>(lp[0].att, 4, 64);

    for (int L = 0; L < 3; L++) {
        const LP& p = lp[L];
        int outdim = p.heads * p.out_c;                     // 256, 128, 64

        if (L > 0) {
            if (outdim >= 128) {
                dim3 ggrid((NN + 127) / 128, outdim / 128);
                gemm128_kernel<<<ggrid, 256>>>(x, 0, p.W, p.K, outdim);
            } else {
                dim3 ggrid((NN + 127) / 128, outdim / 64);
                gemm64_kernel<<<ggrid, 256>>>(x, 0, p.W, p.K, outdim);
            }
            att_node_kernel<<<(NN * p.heads * 32 + 255) / 256, 256>>>(p.att, p.heads, p.out_c);
        }

        cudaStreamWaitEvent(0, evReal[L], 0);
        cudaStreamWaitEvent(0, evSelf[L], 0);   // also covers scatter (g_perm)
        edge_fin_kernel<<<(EL + 255) / 256, 256>>>(src, dst, p.heads, L);

        if (L == 0) {
            int nwarp = NN * 2;          // WPN=2
            agg4_kernel<<<(nwarp + 7) / 8, 256>>>(1, 256, 4, 6,
                                                  p.bias, p.gamma, p.beta, p.mean, p.var);
        } else if (L == 1) {
            int nwarp = NN;              // WPN=1
            agg4_kernel<<<(nwarp + 7) / 8, 256>>>(0, 128, 4, 5,
                                                  p.bias, p.gamma, p.beta, p.mean, p.var);
        } else {
            agg2_kernel<<<(NN + 7) / 8, 256>>>(p.bias, (float*)d_out);
        }
    }
}